// round 11
// baseline (speedup 1.0000x reference)
#include <cuda_runtime.h>
#include <cuda_fp16.h>
#include <mma.h>
#include <cfloat>
#include <cstdint>
#include <math.h>

using namespace nvcuda;
typedef __half h16;

#define SQ   1024
#define NH   128
#define DQ   192
#define DN   128
#define DR   64
#define DV   128
#define HID  7168
#define QLORA 1536
#define KVLORA 512
#define KVAP 640            // padded kv_a width (576 -> 640)
#define DPN  (QLORA + KVAP) // combined down-proj width = 2176 (17 * 128)

// ---------------- scratch (device globals; allocation-free rule) -------------
__device__ float g_qkva[2 * SQ * DPN];    // split-K partials: [qa|kva] x2
__device__ float g_kpe[SQ * DR];

// fp16 activations
__device__ h16 g_xh[SQ * HID],  g_xl[SQ * HID];
__device__ h16 g_qkvah[SQ * DPN];
__device__ h16 g_q16[SQ * NH * DQ];             // q_b output (fp16), roped in place
__device__ h16 g_kv16[SQ * NH * 256];           // kv_b output (fp16)
__device__ h16 g_kh[(long long)NH * SQ * DQ];
__device__ h16 g_Ph[(long long)NH * SQ * SQ];   // scores (unscaled) then P, in-place
__device__ h16 g_aoh[SQ * NH * DV];             // attn out, fp16

// fp16 transposed weights ([N][K] K-major)
__device__ h16 g_Wdt_h[(long long)DPN * HID];   // [Wqa|Wkva]^T
__device__ h16 g_Wqb_t_h[NH * DQ * QLORA];
__device__ h16 g_Wkvb_t_h[NH * 256 * KVLORA];
__device__ h16 g_Wo_t_h[(long long)HID * NH * DV];
__device__ h16 g_Vt_h[(long long)NH * DV * SQ];

// ---------------- helpers -----------------------------------------------------
__device__ __forceinline__ void cp16(const h16* smem_dst, const h16* gsrc) {
    unsigned int saddr = (unsigned int)__cvta_generic_to_shared(smem_dst);
    asm volatile("cp.async.cg.shared.global [%0], [%1], 16;\n" :: "r"(saddr), "l"(gsrc));
}

// ---------------- mixed-term fp16 GEMM -----------------------------------------
// C[M,N] = A[M,K] @ B[N,K]^T  (K-major fp16; batch via blockIdx.z)
// Terms: Ah*Bh  (+ Al*Bh if TA==2)  (+ Ah*Bl if TB==2)
// HOUT: write fp16 (via smem staging) instead of fp32. OCC: min CTAs/SM hint.
template <int TA, int TB, bool CSKIP, bool KLIM, bool HOUT, int OCC>
__global__ void __launch_bounds__(256, (TA + TB == 4) ? 1 : OCC)
gemmH(const h16* __restrict__ Ah, const h16* __restrict__ Al,
      const h16* __restrict__ Bh, const h16* __restrict__ Bl,
      float* __restrict__ C, int K, int lda, int ldb, int ldc,
      long long sA, long long sB, long long sC)
{
    constexpr int PITCH  = 72;           // 64 + 8 pad
    constexpr int BUF    = 128 * PITCH;
    constexpr int NBUF   = TA + TB;
    constexpr int NSTAGE = (NBUF == 4) ? 3 : 2;
    constexpr int STAGE  = NBUF * BUF;

    const int m0 = blockIdx.y << 7, n0 = blockIdx.x << 7;
    if (CSKIP && n0 >= m0 + 128) return;
    const int b = blockIdx.z;
    Ah += (long long)b * sA;
    if (TA == 2) Al += (long long)b * sA;
    Bh += (long long)b * sB;
    if (TB == 2) Bl += (long long)b * sB;
    const long long coff = (long long)b * sC;
    const int Kend = KLIM ? ((m0 + 128 < K) ? m0 + 128 : K) : K;
    const int nK = Kend >> 6;

    extern __shared__ h16 sm[];
    const int tid = threadIdx.x, wid = tid >> 5;
    const int wm = (wid & 3) << 5;
    const int wn = (wid >> 2) << 6;

    auto load_stage = [&](int st, int kc) {
        const int k0 = kc << 6;
        h16* base = sm + st * STAGE;
        #pragma unroll
        for (int i = 0; i < NBUF * 4; i++) {
            int c   = tid + (i << 8);
            int buf = c >> 10;
            int r   = (c >> 3) & 127;
            int k8  = (c & 7) << 3;
            h16* dst = base + buf * BUF + r * PITCH + k8;
            long long offA = (long long)(m0 + r) * lda + k0 + k8;
            long long offB = (long long)(n0 + r) * ldb + k0 + k8;
            const h16* g;
            if (TA == 2) {
                if      (buf == 0) g = Ah + offA;
                else if (buf == 1) g = Al + offA;
                else if (buf == 2) g = Bh + offB;
                else               g = Bl + offB;
            } else {
                if      (buf == 0) g = Ah + offA;
                else if (buf == 1) g = Bh + offB;
                else               g = Bl + offB;
            }
            cp16(dst, g);
        }
        asm volatile("cp.async.commit_group;");
    };

    wmma::fragment<wmma::accumulator, 16, 16, 16, float> acc[2][4];
    #pragma unroll
    for (int i = 0; i < 2; i++)
        #pragma unroll
        for (int j = 0; j < 4; j++)
            wmma::fill_fragment(acc[i][j], 0.0f);

    auto compute = [&](int st) {
        const h16* base = sm + st * STAGE;
        const h16* sAh_ = base;
        const h16* sAl_ = base + BUF;                 // valid iff TA==2
        const h16* sBh_ = base + TA * BUF;
        const h16* sBl_ = base + (TA + 1) * BUF;      // valid iff TB==2
        #pragma unroll
        for (int kk = 0; kk < 4; kk++) {
            const int ko = kk << 4;
            wmma::fragment<wmma::matrix_a, 16, 16, 16, h16, wmma::row_major> ah[2], al[2];
            #pragma unroll
            for (int i = 0; i < 2; i++) {
                wmma::load_matrix_sync(ah[i], sAh_ + (wm + (i << 4)) * PITCH + ko, PITCH);
                if (TA == 2)
                    wmma::load_matrix_sync(al[i], sAl_ + (wm + (i << 4)) * PITCH + ko, PITCH);
            }
            #pragma unroll
            for (int j = 0; j < 4; j++) {
                wmma::fragment<wmma::matrix_b, 16, 16, 16, h16, wmma::col_major> bf;
                wmma::load_matrix_sync(bf, sBh_ + (wn + (j << 4)) * PITCH + ko, PITCH);
                #pragma unroll
                for (int i = 0; i < 2; i++) {
                    wmma::mma_sync(acc[i][j], ah[i], bf, acc[i][j]);
                    if (TA == 2) wmma::mma_sync(acc[i][j], al[i], bf, acc[i][j]);
                }
                if (TB == 2) {
                    wmma::load_matrix_sync(bf, sBl_ + (wn + (j << 4)) * PITCH + ko, PITCH);
                    #pragma unroll
                    for (int i = 0; i < 2; i++)
                        wmma::mma_sync(acc[i][j], ah[i], bf, acc[i][j]);
                }
            }
        }
    };

    if (NSTAGE == 2) {
        load_stage(0, 0);
        for (int kt = 0; kt < nK; kt++) {
            if (kt + 1 < nK) {
                load_stage((kt + 1) & 1, kt + 1);
                asm volatile("cp.async.wait_group 1;");
            } else {
                asm volatile("cp.async.wait_group 0;");
            }
            __syncthreads();
            compute(kt & 1);
            __syncthreads();
        }
    } else {
        load_stage(0, 0);
        if (nK > 1) load_stage(1, 1);
        for (int kt = 0; kt < nK; kt++) {
            if (kt == nK - 1) asm volatile("cp.async.wait_group 0;");
            else              asm volatile("cp.async.wait_group 1;");
            __syncthreads();
            compute(kt % 3);
            __syncthreads();
            if (kt + 2 < nK) load_stage((kt + 2) % 3, kt + 2);
        }
    }

    if (!HOUT) {
        float* Cf = C + coff;
        #pragma unroll
        for (int i = 0; i < 2; i++)
            #pragma unroll
            for (int j = 0; j < 4; j++)
                wmma::store_matrix_sync(
                    &Cf[(long long)(m0 + wm + (i << 4)) * ldc + n0 + wn + (j << 4)],
                    acc[i][j], ldc, wmma::mem_row_major);
    } else {
        // stage fp32 acc in smem, emit coalesced fp16
        float* smf = (float*)sm;   // 128 x 132 floats = 67584 B <= stage smem
        #pragma unroll
        for (int i = 0; i < 2; i++)
            #pragma unroll
            for (int j = 0; j < 4; j++)
                wmma::store_matrix_sync(
                    &smf[(wm + (i << 4)) * 132 + wn + (j << 4)],
                    acc[i][j], 132, wmma::mem_row_major);
        __syncthreads();
        h16* Ch = (h16*)C + coff;
        #pragma unroll
        for (int it = 0; it < 64; it++) {
            int idx = tid + (it << 8);
            int m = idx >> 7, n = idx & 127;
            Ch[(long long)(m0 + m) * ldc + n0 + n] = __float2half_rn(smf[m * 132 + n]);
        }
    }
}

template <int TA, int TB, bool CSKIP, bool KLIM, bool HOUT, int OCC>
static void rung(const h16* Ah, const h16* Al, const h16* Bh, const h16* Bl,
                 float* C, int M, int N, int K, int lda, int ldb, int ldc,
                 long long sA, long long sB, long long sC, int batch)
{
    constexpr int NBUF   = TA + TB;
    constexpr int NSTAGE = (NBUF == 4) ? 3 : 2;
    size_t smem = (size_t)NSTAGE * NBUF * 128 * 72 * sizeof(h16);
    if (HOUT && smem < 128 * 132 * sizeof(float)) smem = 128 * 132 * sizeof(float);
    cudaFuncSetAttribute(gemmH<TA, TB, CSKIP, KLIM, HOUT, OCC>,
                         cudaFuncAttributeMaxDynamicSharedMemorySize, (int)smem);
    dim3 grid(N / 128, M / 128, batch);
    gemmH<TA, TB, CSKIP, KLIM, HOUT, OCC><<<grid, 256, smem>>>(Ah, Al, Bh, Bl, C,
                                                               K, lda, ldb, ldc, sA, sB, sC);
}

// ---------------- split fp32 -> fp16 hi (+ optional lo) ------------------------
template <bool LO>
__global__ void split_kernel(const float4* __restrict__ src,
                             __half2* __restrict__ h,
                             __half2* __restrict__ l, int n4)
{
    int i = blockIdx.x * blockDim.x + threadIdx.x;
    if (i >= n4) return;
    float4 v = src[i];
    h16 h0 = __float2half_rn(v.x), h1 = __float2half_rn(v.y);
    h16 h2 = __float2half_rn(v.z), h3 = __float2half_rn(v.w);
    h[2*i]   = __halves2half2(h0, h1);
    h[2*i+1] = __halves2half2(h2, h3);
    if (LO) {
        h16 l0 = __float2half_rn(v.x - __half2float(h0));
        h16 l1 = __float2half_rn(v.y - __half2float(h1));
        h16 l2 = __float2half_rn(v.z - __half2float(h2));
        h16 l3 = __float2half_rn(v.w - __half2float(h3));
        l[2*i]   = __halves2half2(l0, l1);
        l[2*i+1] = __halves2half2(l2, l3);
    }
}
template <bool LO>
static void split(const float* src, h16* h, h16* l, long long n)
{
    int n4 = (int)(n / 4);
    split_kernel<LO><<<(n4 + 255) / 256, 256>>>((const float4*)src,
                                                (__half2*)h, (__half2*)l, n4);
}

// ---------------- transpose + convert: src[R][C] (T) -> dst[C][R] fp16 ----------
template <typename T>
__global__ void tconv_kernel(const T* __restrict__ src, int ld_src,
                             h16* __restrict__ dh,
                             int ld_dst, long long sSrc, long long sDst)
{
    __shared__ float t[32][33];
    const T* s = src + (long long)blockIdx.z * sSrc;
    h16* oh = dh + (long long)blockIdx.z * sDst;
    int r0 = blockIdx.x * 32;
    int c0 = blockIdx.y * 32;
    int tx = threadIdx.x, ty = threadIdx.y;
    #pragma unroll
    for (int j = 0; j < 4; j++)
        t[ty + j * 8][tx] = (float)s[(long long)(r0 + ty + j * 8) * ld_src + c0 + tx];
    __syncthreads();
    #pragma unroll
    for (int j = 0; j < 4; j++) {
        float v = t[tx][ty + j * 8];
        long long o = (long long)(c0 + ty + j * 8) * ld_dst + r0 + tx;
        oh[o] = __float2half_rn(v);
    }
}
template <typename T>
static void tconv(const T* src, int R, int Cc, int ld_src,
                  h16* dh, int ld_dst, long long sSrc, long long sDst, int batch)
{
    dim3 grid(R / 32, Cc / 32, batch), block(32, 8);
    tconv_kernel<T><<<grid, block>>>(src, ld_src, dh, ld_dst, sSrc, sDst);
}

// ---------------- rmsnorm over sum of two split-K partials (writes buf0) -------
__global__ void rmsnorm2_kernel(float* __restrict__ x0, const float* __restrict__ x1,
                                const float* __restrict__ w, int len, int stride)
{
    float* row0 = x0 + (long long)blockIdx.x * stride;
    const float* row1 = x1 + (long long)blockIdx.x * stride;
    __shared__ float red[256];
    int tid = threadIdx.x;
    float ss = 0.f;
    for (int j = tid; j < len; j += 256) { float v = row0[j] + row1[j]; ss += v * v; }
    red[tid] = ss; __syncthreads();
    for (int s = 128; s > 0; s >>= 1) {
        if (tid < s) red[tid] += red[tid + s];
        __syncthreads();
    }
    float rr = rsqrtf(red[0] / (float)len + 1e-6f);
    for (int j = tid; j < len; j += 256) row0[j] = (row0[j] + row1[j]) * rr * w[j];
}

// ---------------- RoPE ----------------------------------------------------------
// q in fp16 [s][h*192], rope dims 128..191, in place (fp32 math)
__global__ void rope_q16_kernel(h16* __restrict__ q)
{
    int idx = blockIdx.x * blockDim.x + threadIdx.x;
    if (idx >= SQ * NH * 32) return;
    int dp = idx & 31;
    int h  = (idx >> 5) & 127;
    int s  = idx >> 12;
    float a = (float)s * __expf(-(float)dp * (logf(10000.f) / 32.f));
    float c, sn;
    sincosf(a, &sn, &c);
    h16* base = q + (long long)s * (NH * DQ) + h * DQ + DN;
    float x1 = __half2float(base[dp]), x2 = __half2float(base[dp + 32]);
    base[dp]      = __float2half_rn(x1 * c - x2 * sn);
    base[dp + 32] = __float2half_rn(x2 * c + x1 * sn);
}
// k_pe from sum of two split-K partials (pre-norm cols), stride DPN
__global__ void rope_kpe2_kernel(const float* __restrict__ a0,
                                 const float* __restrict__ a1,
                                 int stride, float* __restrict__ kpe)
{
    int idx = blockIdx.x * blockDim.x + threadIdx.x;
    if (idx >= SQ * 32) return;
    int dp = idx & 31;
    int s  = idx >> 5;
    float a = (float)s * __expf(-(float)dp * (logf(10000.f) / 32.f));
    float c, sn;
    sincosf(a, &sn, &c);
    long long o = (long long)s * stride;
    float x1 = a0[o + dp]      + a1[o + dp];
    float x2 = a0[o + dp + 32] + a1[o + dp + 32];
    kpe[s * DR + dp]      = x1 * c - x2 * sn;
    kpe[s * DR + dp + 32] = x2 * c + x1 * sn;
}

// ---------------- assemble K_full from fp16 kv + fp32 kpe ----------------------
__global__ void assemble_k16_kernel(const h16* __restrict__ kv,
                                    const float* __restrict__ kpe,
                                    h16* __restrict__ kh)
{
    long long idx = (long long)blockIdx.x * blockDim.x + threadIdx.x;
    if (idx >= (long long)NH * SQ * DQ) return;
    int d = (int)(idx % DQ);
    int j = (int)((idx / DQ) % SQ);
    int h = (int)(idx / ((long long)DQ * SQ));
    if (d < DN) kh[idx] = kv[(long long)j * (NH * 256) + h * 256 + d];
    else        kh[idx] = __float2half_rn(kpe[j * DR + (d - DN)]);
}

// ---------------- causal softmax, fp16 in-place (scores -> P) ------------------
__global__ void softmax_p_kernel(h16* __restrict__ S)
{
    int r = blockIdx.x;                 // h*1024 + i
    int i = r & (SQ - 1);
    h16* row = S + (long long)r * SQ;
    const float scale = 0.07216878365f; // 1/sqrt(192)
    const int jmax = ((i >> 7) + 1) << 7;  // PV reads k < this bound
    int tid = threadIdx.x;
    int lane = tid & 31, warp = tid >> 5;
    __shared__ float redm[8], reds[8];

    float v[4];
    #pragma unroll
    for (int t = 0; t < 4; t++) {
        int j = tid + t * 256;
        v[t] = (j <= i) ? __half2float(row[j]) * scale : -FLT_MAX;
    }
    float mx = fmaxf(fmaxf(v[0], v[1]), fmaxf(v[2], v[3]));
    #pragma unroll
    for (int o = 16; o > 0; o >>= 1) mx = fmaxf(mx, __shfl_xor_sync(~0u, mx, o));
    if (lane == 0) redm[warp] = mx;
    __syncthreads();
    mx = redm[0];
    #pragma unroll
    for (int w = 1; w < 8; w++) mx = fmaxf(mx, redm[w]);

    float e[4];
    float sum = 0.f;
    #pragma unroll
    for (int t = 0; t < 4; t++) {
        int j = tid + t * 256;
        e[t] = (j <= i) ? __expf(v[t] - mx) : 0.f;
        sum += e[t];
    }
    #pragma unroll
    for (int o = 16; o > 0; o >>= 1) sum += __shfl_xor_sync(~0u, sum, o);
    if (lane == 0) reds[warp] = sum;
    __syncthreads();
    sum = 0.f;
    #pragma unroll
    for (int w = 0; w < 8; w++) sum += reds[w];
    float inv = 1.f / sum;

    #pragma unroll
    for (int t = 0; t < 4; t++) {
        int j = tid + t * 256;
        if (j < jmax) row[j] = __float2half_rn(e[t] * inv);
    }
}

// ---------------- host side -----------------------------------------------------
extern "C" void kernel_launch(void* const* d_in, const int* in_sizes, int n_in,
                              void* d_out, int out_size)
{
    const float* x     = (const float*)d_in[0];
    const float* Wqa   = (const float*)d_in[2];   // [7168,1536]
    const float* wqln  = (const float*)d_in[3];
    const float* Wqb   = (const float*)d_in[4];   // [1536,24576]
    const float* Wkva  = (const float*)d_in[5];   // [7168,576]
    const float* wkvln = (const float*)d_in[6];
    const float* Wkvb  = (const float*)d_in[7];   // [512,32768]
    const float* Wo    = (const float*)d_in[8];   // [16384,7168]
    float*       out   = (float*)d_out;

    float *qkva, *kpe;
    cudaGetSymbolAddress((void**)&qkva, g_qkva);
    cudaGetSymbolAddress((void**)&kpe,  g_kpe);
    float* qkva1 = qkva + (long long)SQ * DPN;   // second split-K partial

    h16 *xh,*xl,*qkvah,*q16,*kv16,*kh,*Phb,*aoh;
    h16 *Wdt_h,*Wqbt_h,*Wkvbt_h,*Wot_h,*Vt_h;
    cudaGetSymbolAddress((void**)&xh,    g_xh);    cudaGetSymbolAddress((void**)&xl,    g_xl);
    cudaGetSymbolAddress((void**)&qkvah, g_qkvah);
    cudaGetSymbolAddress((void**)&q16,   g_q16);
    cudaGetSymbolAddress((void**)&kv16,  g_kv16);
    cudaGetSymbolAddress((void**)&kh,    g_kh);
    cudaGetSymbolAddress((void**)&Phb,   g_Ph);
    cudaGetSymbolAddress((void**)&aoh,   g_aoh);
    cudaGetSymbolAddress((void**)&Wdt_h, g_Wdt_h);
    cudaGetSymbolAddress((void**)&Wqbt_h,  g_Wqb_t_h);
    cudaGetSymbolAddress((void**)&Wkvbt_h, g_Wkvb_t_h);
    cudaGetSymbolAddress((void**)&Wot_h,   g_Wo_t_h);
    cudaGetSymbolAddress((void**)&Vt_h,    g_Vt_h);

    // 0) split x (hi+lo); transpose+convert weights into [N][K] K-major fp16
    split<true>(x, xh, xl, (long long)SQ * HID);
    tconv<float>(Wqa,  HID,    QLORA,    QLORA,    Wdt_h,                        HID,    0, 0, 1);
    tconv<float>(Wkva, HID,    576,      576,      Wdt_h + (long long)QLORA*HID, HID,    0, 0, 1);
    tconv<float>(Wqb,  QLORA,  NH * DQ,  NH * DQ,  Wqbt_h,  QLORA,  0, 0, 1);
    tconv<float>(Wkvb, KVLORA, NH * 256, NH * 256, Wkvbt_h, KVLORA, 0, 0, 1);
    tconv<float>(Wo,   NH*DV,  HID,      HID,      Wot_h,   NH*DV,  0, 0, 1);

    // 1) combined down-projection (2,1), split-K=2 via batch axis (272 CTAs)
    rung<2,1,false,false,false,2>(xh, xl, Wdt_h, Wdt_h, qkva,
        SQ, DPN, HID / 2, HID, HID, DPN,
        HID / 2, HID / 2, (long long)SQ * DPN, 2);

    // 2) k_pe rope from partial sums; rmsnorms over partial sums (write buf0)
    rope_kpe2_kernel<<<(SQ * 32 + 255) / 256, 256>>>(
        qkva + QLORA + KVLORA, qkva1 + QLORA + KVLORA, DPN, kpe);
    rmsnorm2_kernel<<<SQ, 256>>>(qkva,         qkva1,         wqln,  QLORA,  DPN);
    rmsnorm2_kernel<<<SQ, 256>>>(qkva + QLORA, qkva1 + QLORA, wkvln, KVLORA, DPN);

    // 3) convert activations; up-projections (1,1) with fp16 output
    split<false>(qkva, qkvah, qkvah, (long long)SQ * DPN);
    rung<1,1,false,false,true,2>(qkvah, qkvah, Wqbt_h, Wqbt_h, (float*)q16,
        SQ, NH * DQ, QLORA, DPN, QLORA, NH * DQ, 0, 0, 0, 1);
    rung<1,1,false,false,true,2>(qkvah + QLORA, qkvah + QLORA, Wkvbt_h, Wkvbt_h, (float*)kv16,
        SQ, NH * 256, KVLORA, DPN, KVLORA, NH * 256, 0, 0, 0, 1);

    // 4) RoPE on fp16 q (in place); K assembly + V transpose from fp16 kv
    rope_q16_kernel<<<(SQ * NH * 32 + 255) / 256, 256>>>(q16);
    assemble_k16_kernel<<<(int)(((long long)NH * SQ * DQ + 255) / 256), 256>>>(kv16, kpe, kh);
    tconv<h16>(kv16 + DN, SQ, DV, NH * 256, Vt_h, SQ, 256, (long long)DV * SQ, NH);

    // 5) scores = Q @ K^T (1,1), causal tile-skip, fp16 out into P buffer
    rung<1,1,true,false,true,2>(q16, q16, kh, kh, (float*)Phb,
        SQ, SQ, DQ, NH * DQ, DQ, SQ,
        DQ, (long long)SQ * DQ, (long long)SQ * SQ, NH);

    // 6) causal softmax, fp16 in-place (scores -> P)
    softmax_p_kernel<<<NH * SQ, 256>>>(Phb);

    // 7) out_h = P @ V (1,1), k-limited, fp16 out -> aoh
    rung<1,1,false,true,true,2>(Phb, Phb, Vt_h, Vt_h, (float*)aoh,
        SQ, DV, SQ, SQ, SQ, NH * DV,
        (long long)SQ * SQ, (long long)DV * SQ, DV, NH);

    // 8) output projection (1,1), occupancy 3 (448 CTAs -> ~1 wave)
    rung<1,1,false,false,false,3>(aoh, aoh, Wot_h, Wot_h, out,
        SQ, HID, NH * DV, NH * DV, NH * DV, HID, 0, 0, 0, 1);
}

// round 12
// speedup vs baseline: 1.3748x; 1.3748x over previous
#include <cuda_runtime.h>
#include <cuda_fp16.h>
#include <mma.h>
#include <cfloat>
#include <cstdint>
#include <math.h>

using namespace nvcuda;
typedef __half h16;

#define SQ   1024
#define NH   128
#define DQ   192
#define DN   128
#define DR   64
#define DV   128
#define HID  7168
#define QLORA 1536
#define KVLORA 512
#define KVAP 640            // padded kv_a width (576 -> 640)
#define DPN  (QLORA + KVAP) // combined down-proj width = 2176 (17 * 128)

// ---------------- scratch (device globals; allocation-free rule) -------------
__device__ float g_qkva[2 * SQ * DPN];    // split-K partials: [qa|kva] x2
__device__ float g_kpe[SQ * DR];

// fp16 activations
__device__ h16 g_xh[SQ * HID],  g_xl[SQ * HID];
__device__ h16 g_qkvah[SQ * DPN];
__device__ h16 g_q16[SQ * NH * DQ];             // q_b output (fp16), roped in place
__device__ h16 g_kv16[SQ * NH * 256];           // kv_b output (fp16)
__device__ h16 g_kh[(long long)NH * SQ * DQ];
__device__ h16 g_Ph[(long long)NH * SQ * SQ];   // scores (unscaled) then P, in-place
__device__ h16 g_aoh[SQ * NH * DV];             // attn out, fp16

// fp16 transposed weights ([N][K] K-major)
__device__ h16 g_Wdt_h[(long long)DPN * HID];   // [Wqa|Wkva]^T
__device__ h16 g_Wqb_t_h[NH * DQ * QLORA];
__device__ h16 g_Wkvb_t_h[NH * 256 * KVLORA];
__device__ h16 g_Wo_t_h[(long long)HID * NH * DV];
__device__ h16 g_Vt_h[(long long)NH * DV * SQ];

// ---------------- helpers -----------------------------------------------------
__device__ __forceinline__ void cp16(const h16* smem_dst, const h16* gsrc) {
    unsigned int saddr = (unsigned int)__cvta_generic_to_shared(smem_dst);
    asm volatile("cp.async.cg.shared.global [%0], [%1], 16;\n" :: "r"(saddr), "l"(gsrc));
}

// ---------------- mixed-term fp16 GEMM -----------------------------------------
// C[M,N] = A[M,K] @ B[N,K]^T  (K-major fp16; batch via blockIdx.z)
// Terms: Ah*Bh  (+ Al*Bh if TA==2)  (+ Ah*Bl if TB==2)
// HOUT: write fp16 (via smem staging) instead of fp32.
template <int TA, int TB, bool CSKIP, bool KLIM, bool HOUT>
__global__ void __launch_bounds__(256, (TA + TB == 4) ? 1 : 2)
gemmH(const h16* __restrict__ Ah, const h16* __restrict__ Al,
      const h16* __restrict__ Bh, const h16* __restrict__ Bl,
      float* __restrict__ C, int K, int lda, int ldb, int ldc,
      long long sA, long long sB, long long sC)
{
    constexpr int PITCH  = 72;           // 64 + 8 pad
    constexpr int BUF    = 128 * PITCH;
    constexpr int NBUF   = TA + TB;
    constexpr int NSTAGE = (NBUF == 4) ? 3 : 2;
    constexpr int STAGE  = NBUF * BUF;

    const int m0 = blockIdx.y << 7, n0 = blockIdx.x << 7;
    if (CSKIP && n0 >= m0 + 128) return;
    const int b = blockIdx.z;
    Ah += (long long)b * sA;
    if (TA == 2) Al += (long long)b * sA;
    Bh += (long long)b * sB;
    if (TB == 2) Bl += (long long)b * sB;
    const long long coff = (long long)b * sC;
    const int Kend = KLIM ? ((m0 + 128 < K) ? m0 + 128 : K) : K;
    const int nK = Kend >> 6;

    extern __shared__ h16 sm[];
    const int tid = threadIdx.x, wid = tid >> 5;
    const int wm = (wid & 3) << 5;
    const int wn = (wid >> 2) << 6;

    auto load_stage = [&](int st, int kc) {
        const int k0 = kc << 6;
        h16* base = sm + st * STAGE;
        #pragma unroll
        for (int i = 0; i < NBUF * 4; i++) {
            int c   = tid + (i << 8);
            int buf = c >> 10;
            int r   = (c >> 3) & 127;
            int k8  = (c & 7) << 3;
            h16* dst = base + buf * BUF + r * PITCH + k8;
            long long offA = (long long)(m0 + r) * lda + k0 + k8;
            long long offB = (long long)(n0 + r) * ldb + k0 + k8;
            const h16* g;
            if (TA == 2) {
                if      (buf == 0) g = Ah + offA;
                else if (buf == 1) g = Al + offA;
                else if (buf == 2) g = Bh + offB;
                else               g = Bl + offB;
            } else {
                if      (buf == 0) g = Ah + offA;
                else if (buf == 1) g = Bh + offB;
                else               g = Bl + offB;
            }
            cp16(dst, g);
        }
        asm volatile("cp.async.commit_group;");
    };

    wmma::fragment<wmma::accumulator, 16, 16, 16, float> acc[2][4];
    #pragma unroll
    for (int i = 0; i < 2; i++)
        #pragma unroll
        for (int j = 0; j < 4; j++)
            wmma::fill_fragment(acc[i][j], 0.0f);

    auto compute = [&](int st) {
        const h16* base = sm + st * STAGE;
        const h16* sAh_ = base;
        const h16* sAl_ = base + BUF;                 // valid iff TA==2
        const h16* sBh_ = base + TA * BUF;
        const h16* sBl_ = base + (TA + 1) * BUF;      // valid iff TB==2
        #pragma unroll
        for (int kk = 0; kk < 4; kk++) {
            const int ko = kk << 4;
            wmma::fragment<wmma::matrix_a, 16, 16, 16, h16, wmma::row_major> ah[2], al[2];
            #pragma unroll
            for (int i = 0; i < 2; i++) {
                wmma::load_matrix_sync(ah[i], sAh_ + (wm + (i << 4)) * PITCH + ko, PITCH);
                if (TA == 2)
                    wmma::load_matrix_sync(al[i], sAl_ + (wm + (i << 4)) * PITCH + ko, PITCH);
            }
            #pragma unroll
            for (int j = 0; j < 4; j++) {
                wmma::fragment<wmma::matrix_b, 16, 16, 16, h16, wmma::col_major> bf;
                wmma::load_matrix_sync(bf, sBh_ + (wn + (j << 4)) * PITCH + ko, PITCH);
                #pragma unroll
                for (int i = 0; i < 2; i++) {
                    wmma::mma_sync(acc[i][j], ah[i], bf, acc[i][j]);
                    if (TA == 2) wmma::mma_sync(acc[i][j], al[i], bf, acc[i][j]);
                }
                if (TB == 2) {
                    wmma::load_matrix_sync(bf, sBl_ + (wn + (j << 4)) * PITCH + ko, PITCH);
                    #pragma unroll
                    for (int i = 0; i < 2; i++)
                        wmma::mma_sync(acc[i][j], ah[i], bf, acc[i][j]);
                }
            }
        }
    };

    if (NSTAGE == 2) {
        load_stage(0, 0);
        for (int kt = 0; kt < nK; kt++) {
            if (kt + 1 < nK) {
                load_stage((kt + 1) & 1, kt + 1);
                asm volatile("cp.async.wait_group 1;");
            } else {
                asm volatile("cp.async.wait_group 0;");
            }
            __syncthreads();
            compute(kt & 1);
            __syncthreads();
        }
    } else {
        load_stage(0, 0);
        if (nK > 1) load_stage(1, 1);
        for (int kt = 0; kt < nK; kt++) {
            if (kt == nK - 1) asm volatile("cp.async.wait_group 0;");
            else              asm volatile("cp.async.wait_group 1;");
            __syncthreads();
            compute(kt % 3);
            __syncthreads();
            if (kt + 2 < nK) load_stage((kt + 2) % 3, kt + 2);
        }
    }

    if (!HOUT) {
        float* Cf = C + coff;
        #pragma unroll
        for (int i = 0; i < 2; i++)
            #pragma unroll
            for (int j = 0; j < 4; j++)
                wmma::store_matrix_sync(
                    &Cf[(long long)(m0 + wm + (i << 4)) * ldc + n0 + wn + (j << 4)],
                    acc[i][j], ldc, wmma::mem_row_major);
    } else {
        // stage fp32 acc in smem, emit coalesced fp16
        float* smf = (float*)sm;   // 128 x 132 floats = 67584 B <= stage smem
        #pragma unroll
        for (int i = 0; i < 2; i++)
            #pragma unroll
            for (int j = 0; j < 4; j++)
                wmma::store_matrix_sync(
                    &smf[(wm + (i << 4)) * 132 + wn + (j << 4)],
                    acc[i][j], 132, wmma::mem_row_major);
        __syncthreads();
        h16* Ch = (h16*)C + coff;
        #pragma unroll
        for (int it = 0; it < 64; it++) {
            int idx = tid + (it << 8);
            int m = idx >> 7, n = idx & 127;
            Ch[(long long)(m0 + m) * ldc + n0 + n] = __float2half_rn(smf[m * 132 + n]);
        }
    }
}

template <int TA, int TB, bool CSKIP, bool KLIM, bool HOUT>
static void rung(const h16* Ah, const h16* Al, const h16* Bh, const h16* Bl,
                 float* C, int M, int N, int K, int lda, int ldb, int ldc,
                 long long sA, long long sB, long long sC, int batch)
{
    constexpr int NBUF   = TA + TB;
    constexpr int NSTAGE = (NBUF == 4) ? 3 : 2;
    size_t smem = (size_t)NSTAGE * NBUF * 128 * 72 * sizeof(h16);
    if (HOUT && smem < 128 * 132 * sizeof(float)) smem = 128 * 132 * sizeof(float);
    cudaFuncSetAttribute(gemmH<TA, TB, CSKIP, KLIM, HOUT>,
                         cudaFuncAttributeMaxDynamicSharedMemorySize, (int)smem);
    dim3 grid(N / 128, M / 128, batch);
    gemmH<TA, TB, CSKIP, KLIM, HOUT><<<grid, 256, smem>>>(Ah, Al, Bh, Bl, C,
                                                          K, lda, ldb, ldc, sA, sB, sC);
}

// ---------------- split fp32 -> fp16 hi (+ optional lo) ------------------------
template <bool LO>
__global__ void split_kernel(const float4* __restrict__ src,
                             __half2* __restrict__ h,
                             __half2* __restrict__ l, int n4)
{
    int i = blockIdx.x * blockDim.x + threadIdx.x;
    if (i >= n4) return;
    float4 v = src[i];
    h16 h0 = __float2half_rn(v.x), h1 = __float2half_rn(v.y);
    h16 h2 = __float2half_rn(v.z), h3 = __float2half_rn(v.w);
    h[2*i]   = __halves2half2(h0, h1);
    h[2*i+1] = __halves2half2(h2, h3);
    if (LO) {
        h16 l0 = __float2half_rn(v.x - __half2float(h0));
        h16 l1 = __float2half_rn(v.y - __half2float(h1));
        h16 l2 = __float2half_rn(v.z - __half2float(h2));
        h16 l3 = __float2half_rn(v.w - __half2float(h3));
        l[2*i]   = __halves2half2(l0, l1);
        l[2*i+1] = __halves2half2(l2, l3);
    }
}
template <bool LO>
static void split(const float* src, h16* h, h16* l, long long n)
{
    int n4 = (int)(n / 4);
    split_kernel<LO><<<(n4 + 255) / 256, 256>>>((const float4*)src,
                                                (__half2*)h, (__half2*)l, n4);
}

// ---------------- transpose + convert: src[R][C] (T) -> dst[C][R] fp16 ----------
template <typename T>
__global__ void tconv_kernel(const T* __restrict__ src, int ld_src,
                             h16* __restrict__ dh,
                             int ld_dst, long long sSrc, long long sDst)
{
    __shared__ float t[32][33];
    const T* s = src + (long long)blockIdx.z * sSrc;
    h16* oh = dh + (long long)blockIdx.z * sDst;
    int r0 = blockIdx.x * 32;
    int c0 = blockIdx.y * 32;
    int tx = threadIdx.x, ty = threadIdx.y;
    #pragma unroll
    for (int j = 0; j < 4; j++)
        t[ty + j * 8][tx] = (float)s[(long long)(r0 + ty + j * 8) * ld_src + c0 + tx];
    __syncthreads();
    #pragma unroll
    for (int j = 0; j < 4; j++) {
        float v = t[tx][ty + j * 8];
        long long o = (long long)(c0 + ty + j * 8) * ld_dst + r0 + tx;
        oh[o] = __float2half_rn(v);
    }
}
template <typename T>
static void tconv(const T* src, int R, int Cc, int ld_src,
                  h16* dh, int ld_dst, long long sSrc, long long sDst, int batch)
{
    dim3 grid(R / 32, Cc / 32, batch), block(32, 8);
    tconv_kernel<T><<<grid, block>>>(src, ld_src, dh, ld_dst, sSrc, sDst);
}

// ---------------- rmsnorm over sum of two split-K partials (writes buf0) -------
__global__ void rmsnorm2_kernel(float* __restrict__ x0, const float* __restrict__ x1,
                                const float* __restrict__ w, int len, int stride)
{
    float* row0 = x0 + (long long)blockIdx.x * stride;
    const float* row1 = x1 + (long long)blockIdx.x * stride;
    __shared__ float red[256];
    int tid = threadIdx.x;
    float ss = 0.f;
    for (int j = tid; j < len; j += 256) { float v = row0[j] + row1[j]; ss += v * v; }
    red[tid] = ss; __syncthreads();
    for (int s = 128; s > 0; s >>= 1) {
        if (tid < s) red[tid] += red[tid + s];
        __syncthreads();
    }
    float rr = rsqrtf(red[0] / (float)len + 1e-6f);
    for (int j = tid; j < len; j += 256) row0[j] = (row0[j] + row1[j]) * rr * w[j];
}

// ---------------- RoPE ----------------------------------------------------------
// q in fp16 [s][h*192], rope dims 128..191, in place (fp32 math)
__global__ void rope_q16_kernel(h16* __restrict__ q)
{
    int idx = blockIdx.x * blockDim.x + threadIdx.x;
    if (idx >= SQ * NH * 32) return;
    int dp = idx & 31;
    int h  = (idx >> 5) & 127;
    int s  = idx >> 12;
    float a = (float)s * __expf(-(float)dp * (logf(10000.f) / 32.f));
    float c, sn;
    sincosf(a, &sn, &c);
    h16* base = q + (long long)s * (NH * DQ) + h * DQ + DN;
    float x1 = __half2float(base[dp]), x2 = __half2float(base[dp + 32]);
    base[dp]      = __float2half_rn(x1 * c - x2 * sn);
    base[dp + 32] = __float2half_rn(x2 * c + x1 * sn);
}
// k_pe from sum of two split-K partials (pre-norm cols), stride DPN
__global__ void rope_kpe2_kernel(const float* __restrict__ a0,
                                 const float* __restrict__ a1,
                                 int stride, float* __restrict__ kpe)
{
    int idx = blockIdx.x * blockDim.x + threadIdx.x;
    if (idx >= SQ * 32) return;
    int dp = idx & 31;
    int s  = idx >> 5;
    float a = (float)s * __expf(-(float)dp * (logf(10000.f) / 32.f));
    float c, sn;
    sincosf(a, &sn, &c);
    long long o = (long long)s * stride;
    float x1 = a0[o + dp]      + a1[o + dp];
    float x2 = a0[o + dp + 32] + a1[o + dp + 32];
    kpe[s * DR + dp]      = x1 * c - x2 * sn;
    kpe[s * DR + dp + 32] = x2 * c + x1 * sn;
}

// ---------------- assemble K_full from fp16 kv + fp32 kpe ----------------------
__global__ void assemble_k16_kernel(const h16* __restrict__ kv,
                                    const float* __restrict__ kpe,
                                    h16* __restrict__ kh)
{
    long long idx = (long long)blockIdx.x * blockDim.x + threadIdx.x;
    if (idx >= (long long)NH * SQ * DQ) return;
    int d = (int)(idx % DQ);
    int j = (int)((idx / DQ) % SQ);
    int h = (int)(idx / ((long long)DQ * SQ));
    if (d < DN) kh[idx] = kv[(long long)j * (NH * 256) + h * 256 + d];
    else        kh[idx] = __float2half_rn(kpe[j * DR + (d - DN)]);
}

// ---------------- causal softmax, fp16 in-place (scores -> P) ------------------
__global__ void softmax_p_kernel(h16* __restrict__ S)
{
    int r = blockIdx.x;                 // h*1024 + i
    int i = r & (SQ - 1);
    h16* row = S + (long long)r * SQ;
    const float scale = 0.07216878365f; // 1/sqrt(192)
    const int jmax = ((i >> 7) + 1) << 7;  // PV reads k < this bound
    int tid = threadIdx.x;
    int lane = tid & 31, warp = tid >> 5;
    __shared__ float redm[8], reds[8];

    float v[4];
    #pragma unroll
    for (int t = 0; t < 4; t++) {
        int j = tid + t * 256;
        v[t] = (j <= i) ? __half2float(row[j]) * scale : -FLT_MAX;
    }
    float mx = fmaxf(fmaxf(v[0], v[1]), fmaxf(v[2], v[3]));
    #pragma unroll
    for (int o = 16; o > 0; o >>= 1) mx = fmaxf(mx, __shfl_xor_sync(~0u, mx, o));
    if (lane == 0) redm[warp] = mx;
    __syncthreads();
    mx = redm[0];
    #pragma unroll
    for (int w = 1; w < 8; w++) mx = fmaxf(mx, redm[w]);

    float e[4];
    float sum = 0.f;
    #pragma unroll
    for (int t = 0; t < 4; t++) {
        int j = tid + t * 256;
        e[t] = (j <= i) ? __expf(v[t] - mx) : 0.f;
        sum += e[t];
    }
    #pragma unroll
    for (int o = 16; o > 0; o >>= 1) sum += __shfl_xor_sync(~0u, sum, o);
    if (lane == 0) reds[warp] = sum;
    __syncthreads();
    sum = 0.f;
    #pragma unroll
    for (int w = 0; w < 8; w++) sum += reds[w];
    float inv = 1.f / sum;

    #pragma unroll
    for (int t = 0; t < 4; t++) {
        int j = tid + t * 256;
        if (j < jmax) row[j] = __float2half_rn(e[t] * inv);
    }
}

// ---------------- host side -----------------------------------------------------
extern "C" void kernel_launch(void* const* d_in, const int* in_sizes, int n_in,
                              void* d_out, int out_size)
{
    const float* x     = (const float*)d_in[0];
    const float* Wqa   = (const float*)d_in[2];   // [7168,1536]
    const float* wqln  = (const float*)d_in[3];
    const float* Wqb   = (const float*)d_in[4];   // [1536,24576]
    const float* Wkva  = (const float*)d_in[5];   // [7168,576]
    const float* wkvln = (const float*)d_in[6];
    const float* Wkvb  = (const float*)d_in[7];   // [512,32768]
    const float* Wo    = (const float*)d_in[8];   // [16384,7168]
    float*       out   = (float*)d_out;

    float *qkva, *kpe;
    cudaGetSymbolAddress((void**)&qkva, g_qkva);
    cudaGetSymbolAddress((void**)&kpe,  g_kpe);
    float* qkva1 = qkva + (long long)SQ * DPN;   // second split-K partial

    h16 *xh,*xl,*qkvah,*q16,*kv16,*kh,*Phb,*aoh;
    h16 *Wdt_h,*Wqbt_h,*Wkvbt_h,*Wot_h,*Vt_h;
    cudaGetSymbolAddress((void**)&xh,    g_xh);    cudaGetSymbolAddress((void**)&xl,    g_xl);
    cudaGetSymbolAddress((void**)&qkvah, g_qkvah);
    cudaGetSymbolAddress((void**)&q16,   g_q16);
    cudaGetSymbolAddress((void**)&kv16,  g_kv16);
    cudaGetSymbolAddress((void**)&kh,    g_kh);
    cudaGetSymbolAddress((void**)&Phb,   g_Ph);
    cudaGetSymbolAddress((void**)&aoh,   g_aoh);
    cudaGetSymbolAddress((void**)&Wdt_h, g_Wdt_h);
    cudaGetSymbolAddress((void**)&Wqbt_h,  g_Wqb_t_h);
    cudaGetSymbolAddress((void**)&Wkvbt_h, g_Wkvb_t_h);
    cudaGetSymbolAddress((void**)&Wot_h,   g_Wo_t_h);
    cudaGetSymbolAddress((void**)&Vt_h,    g_Vt_h);

    // 0) split x (hi+lo); transpose+convert weights into [N][K] K-major fp16
    split<true>(x, xh, xl, (long long)SQ * HID);
    tconv<float>(Wqa,  HID,    QLORA,    QLORA,    Wdt_h,                        HID,    0, 0, 1);
    tconv<float>(Wkva, HID,    576,      576,      Wdt_h + (long long)QLORA*HID, HID,    0, 0, 1);
    tconv<float>(Wqb,  QLORA,  NH * DQ,  NH * DQ,  Wqbt_h,  QLORA,  0, 0, 1);
    tconv<float>(Wkvb, KVLORA, NH * 256, NH * 256, Wkvbt_h, KVLORA, 0, 0, 1);
    tconv<float>(Wo,   NH*DV,  HID,      HID,      Wot_h,   NH*DV,  0, 0, 1);

    // 1) combined down-projection (2,1), split-K=2 via batch axis (272 CTAs)
    rung<2,1,false,false,false>(xh, xl, Wdt_h, Wdt_h, qkva,
        SQ, DPN, HID / 2, HID, HID, DPN,
        HID / 2, HID / 2, (long long)SQ * DPN, 2);

    // 2) k_pe rope from partial sums; rmsnorms over partial sums (write buf0)
    rope_kpe2_kernel<<<(SQ * 32 + 255) / 256, 256>>>(
        qkva + QLORA + KVLORA, qkva1 + QLORA + KVLORA, DPN, kpe);
    rmsnorm2_kernel<<<SQ, 256>>>(qkva,         qkva1,         wqln,  QLORA,  DPN);
    rmsnorm2_kernel<<<SQ, 256>>>(qkva + QLORA, qkva1 + QLORA, wkvln, KVLORA, DPN);

    // 3) convert activations; up-projections (1,1) with fp16 output
    split<false>(qkva, qkvah, qkvah, (long long)SQ * DPN);
    rung<1,1,false,false,true>(qkvah, qkvah, Wqbt_h, Wqbt_h, (float*)q16,
        SQ, NH * DQ, QLORA, DPN, QLORA, NH * DQ, 0, 0, 0, 1);
    rung<1,1,false,false,true>(qkvah + QLORA, qkvah + QLORA, Wkvbt_h, Wkvbt_h, (float*)kv16,
        SQ, NH * 256, KVLORA, DPN, KVLORA, NH * 256, 0, 0, 0, 1);

    // 4) RoPE on fp16 q (in place); K assembly + V transpose from fp16 kv
    rope_q16_kernel<<<(SQ * NH * 32 + 255) / 256, 256>>>(q16);
    assemble_k16_kernel<<<(int)(((long long)NH * SQ * DQ + 255) / 256), 256>>>(kv16, kpe, kh);
    tconv<h16>(kv16 + DN, SQ, DV, NH * 256, Vt_h, SQ, 256, (long long)DV * SQ, NH);

    // 5) scores = Q @ K^T (1,1), causal tile-skip, fp16 out into P buffer
    rung<1,1,true,false,true>(q16, q16, kh, kh, (float*)Phb,
        SQ, SQ, DQ, NH * DQ, DQ, SQ,
        DQ, (long long)SQ * DQ, (long long)SQ * SQ, NH);

    // 6) causal softmax, fp16 in-place (scores -> P)
    softmax_p_kernel<<<NH * SQ, 256>>>(Phb);

    // 7) out_h = P @ V (1,1), k-limited, fp16 out -> aoh
    rung<1,1,false,true,true>(Phb, Phb, Vt_h, Vt_h, (float*)aoh,
        SQ, DV, SQ, SQ, SQ, NH * DV,
        (long long)SQ * SQ, (long long)DV * SQ, DV, NH);

    // 8) output projection (1,1), occupancy 2 (R10 config — occ3 spilled)
    rung<1,1,false,false,false>(aoh, aoh, Wot_h, Wot_h, out,
        SQ, HID, NH * DV, NH * DV, NH * DV, HID, 0, 0, 0, 1);
}

// round 13
// speedup vs baseline: 1.3761x; 1.0010x over previous
#include <cuda_runtime.h>
#include <cuda_fp16.h>
#include <mma.h>
#include <cfloat>
#include <cstdint>
#include <math.h>

using namespace nvcuda;
typedef __half h16;

#define SQ   1024
#define NH   128
#define DQ   192
#define DN   128
#define DR   64
#define DV   128
#define HID  7168
#define QLORA 1536
#define KVLORA 512
#define KVAP 640            // padded kv_a width (576 -> 640)
#define DPN  (QLORA + KVAP) // combined down-proj width = 2176 (17 * 128)

// ---------------- scratch (device globals; allocation-free rule) -------------
__device__ float g_qkva[2 * SQ * DPN];    // split-K partials: [qa|kva] x2
__device__ float g_kpe[SQ * DR];

// fp16 activations
__device__ h16 g_xh[SQ * HID],  g_xl[SQ * HID];
__device__ h16 g_qkvah[SQ * DPN];
__device__ h16 g_q16[SQ * NH * DQ];             // q_b output (fp16), roped in place
__device__ h16 g_kv16[SQ * NH * 256];           // kv_b output (fp16)
__device__ h16 g_kh[(long long)NH * SQ * DQ];
__device__ h16 g_Ph[(long long)NH * SQ * SQ];   // scores (unscaled) then P, in-place
__device__ h16 g_aoh[SQ * NH * DV];             // attn out, fp16

// fp16 transposed weights ([N][K] K-major)
__device__ h16 g_Wdt_h[(long long)DPN * HID];   // [Wqa|Wkva]^T
__device__ h16 g_Wqb_t_h[NH * DQ * QLORA];
__device__ h16 g_Wkvb_t_h[NH * 256 * KVLORA];
__device__ h16 g_Wo_t_h[(long long)HID * NH * DV];
__device__ h16 g_Vt_h[(long long)NH * DV * SQ];

// ---------------- helpers -----------------------------------------------------
__device__ __forceinline__ void cp16(const h16* smem_dst, const h16* gsrc) {
    unsigned int saddr = (unsigned int)__cvta_generic_to_shared(smem_dst);
    asm volatile("cp.async.cg.shared.global [%0], [%1], 16;\n" :: "r"(saddr), "l"(gsrc));
}

// ---------------- mixed-term fp16 GEMM -----------------------------------------
// C[M,N] = A[M,K] @ B[N,K]^T  (K-major fp16; batch via blockIdx.z)
// Terms: Ah*Bh  (+ Al*Bh if TA==2)  (+ Ah*Bl if TB==2)
// HOUT: write fp16 (via smem staging) instead of fp32.
// NBUF==2 -> 3-stage pipeline (2 loads in flight), occ2.
template <int TA, int TB, bool CSKIP, bool KLIM, bool HOUT>
__global__ void __launch_bounds__(256, (TA + TB == 4) ? 1 : 2)
gemmH(const h16* __restrict__ Ah, const h16* __restrict__ Al,
      const h16* __restrict__ Bh, const h16* __restrict__ Bl,
      float* __restrict__ C, int K, int lda, int ldb, int ldc,
      long long sA, long long sB, long long sC)
{
    constexpr int PITCH  = 72;           // 64 + 8 pad
    constexpr int BUF    = 128 * PITCH;
    constexpr int NBUF   = TA + TB;
    constexpr int NSTAGE = (NBUF == 3) ? 2 : 3;   // NBUF 2 or 4 -> 3 stages
    constexpr int STAGE  = NBUF * BUF;

    const int m0 = blockIdx.y << 7, n0 = blockIdx.x << 7;
    if (CSKIP && n0 >= m0 + 128) return;
    const int b = blockIdx.z;
    Ah += (long long)b * sA;
    if (TA == 2) Al += (long long)b * sA;
    Bh += (long long)b * sB;
    if (TB == 2) Bl += (long long)b * sB;
    const long long coff = (long long)b * sC;
    const int Kend = KLIM ? ((m0 + 128 < K) ? m0 + 128 : K) : K;
    const int nK = Kend >> 6;

    extern __shared__ h16 sm[];
    const int tid = threadIdx.x, wid = tid >> 5;
    const int wm = (wid & 3) << 5;
    const int wn = (wid >> 2) << 6;

    auto load_stage = [&](int st, int kc) {
        const int k0 = kc << 6;
        h16* base = sm + st * STAGE;
        #pragma unroll
        for (int i = 0; i < NBUF * 4; i++) {
            int c   = tid + (i << 8);
            int buf = c >> 10;
            int r   = (c >> 3) & 127;
            int k8  = (c & 7) << 3;
            h16* dst = base + buf * BUF + r * PITCH + k8;
            long long offA = (long long)(m0 + r) * lda + k0 + k8;
            long long offB = (long long)(n0 + r) * ldb + k0 + k8;
            const h16* g;
            if (TA == 2) {
                if      (buf == 0) g = Ah + offA;
                else if (buf == 1) g = Al + offA;
                else if (buf == 2) g = Bh + offB;
                else               g = Bl + offB;
            } else {
                if      (buf == 0) g = Ah + offA;
                else if (buf == 1) g = Bh + offB;
                else               g = Bl + offB;
            }
            cp16(dst, g);
        }
        asm volatile("cp.async.commit_group;");
    };

    wmma::fragment<wmma::accumulator, 16, 16, 16, float> acc[2][4];
    #pragma unroll
    for (int i = 0; i < 2; i++)
        #pragma unroll
        for (int j = 0; j < 4; j++)
            wmma::fill_fragment(acc[i][j], 0.0f);

    auto compute = [&](int st) {
        const h16* base = sm + st * STAGE;
        const h16* sAh_ = base;
        const h16* sAl_ = base + BUF;                 // valid iff TA==2
        const h16* sBh_ = base + TA * BUF;
        const h16* sBl_ = base + (TA + 1) * BUF;      // valid iff TB==2
        #pragma unroll
        for (int kk = 0; kk < 4; kk++) {
            const int ko = kk << 4;
            wmma::fragment<wmma::matrix_a, 16, 16, 16, h16, wmma::row_major> ah[2], al[2];
            #pragma unroll
            for (int i = 0; i < 2; i++) {
                wmma::load_matrix_sync(ah[i], sAh_ + (wm + (i << 4)) * PITCH + ko, PITCH);
                if (TA == 2)
                    wmma::load_matrix_sync(al[i], sAl_ + (wm + (i << 4)) * PITCH + ko, PITCH);
            }
            #pragma unroll
            for (int j = 0; j < 4; j++) {
                wmma::fragment<wmma::matrix_b, 16, 16, 16, h16, wmma::col_major> bf;
                wmma::load_matrix_sync(bf, sBh_ + (wn + (j << 4)) * PITCH + ko, PITCH);
                #pragma unroll
                for (int i = 0; i < 2; i++) {
                    wmma::mma_sync(acc[i][j], ah[i], bf, acc[i][j]);
                    if (TA == 2) wmma::mma_sync(acc[i][j], al[i], bf, acc[i][j]);
                }
                if (TB == 2) {
                    wmma::load_matrix_sync(bf, sBl_ + (wn + (j << 4)) * PITCH + ko, PITCH);
                    #pragma unroll
                    for (int i = 0; i < 2; i++)
                        wmma::mma_sync(acc[i][j], ah[i], bf, acc[i][j]);
                }
            }
        }
    };

    if (NSTAGE == 2) {
        load_stage(0, 0);
        for (int kt = 0; kt < nK; kt++) {
            if (kt + 1 < nK) {
                load_stage((kt + 1) & 1, kt + 1);
                asm volatile("cp.async.wait_group 1;");
            } else {
                asm volatile("cp.async.wait_group 0;");
            }
            __syncthreads();
            compute(kt & 1);
            __syncthreads();
        }
    } else {
        // 3-stage, loads issued two iterations ahead
        load_stage(0, 0);
        if (nK > 1) load_stage(1, 1);
        for (int kt = 0; kt < nK; kt++) {
            if (kt + 2 < nK) {
                load_stage((kt + 2) % 3, kt + 2);
                asm volatile("cp.async.wait_group 2;");
            } else if (kt + 1 < nK) {
                asm volatile("cp.async.wait_group 1;");
            } else {
                asm volatile("cp.async.wait_group 0;");
            }
            __syncthreads();
            compute(kt % 3);
            __syncthreads();
        }
    }

    if (!HOUT) {
        float* Cf = C + coff;
        #pragma unroll
        for (int i = 0; i < 2; i++)
            #pragma unroll
            for (int j = 0; j < 4; j++)
                wmma::store_matrix_sync(
                    &Cf[(long long)(m0 + wm + (i << 4)) * ldc + n0 + wn + (j << 4)],
                    acc[i][j], ldc, wmma::mem_row_major);
    } else {
        // stage fp32 acc in smem, emit coalesced fp16
        float* smf = (float*)sm;   // 128 x 132 floats = 67584 B <= stage smem
        #pragma unroll
        for (int i = 0; i < 2; i++)
            #pragma unroll
            for (int j = 0; j < 4; j++)
                wmma::store_matrix_sync(
                    &smf[(wm + (i << 4)) * 132 + wn + (j << 4)],
                    acc[i][j], 132, wmma::mem_row_major);
        __syncthreads();
        h16* Ch = (h16*)C + coff;
        #pragma unroll
        for (int it = 0; it < 64; it++) {
            int idx = tid + (it << 8);
            int m = idx >> 7, n = idx & 127;
            Ch[(long long)(m0 + m) * ldc + n0 + n] = __float2half_rn(smf[m * 132 + n]);
        }
    }
}

template <int TA, int TB, bool CSKIP, bool KLIM, bool HOUT>
static void rung(const h16* Ah, const h16* Al, const h16* Bh, const h16* Bl,
                 float* C, int M, int N, int K, int lda, int ldb, int ldc,
                 long long sA, long long sB, long long sC, int batch)
{
    constexpr int NBUF   = TA + TB;
    constexpr int NSTAGE = (NBUF == 3) ? 2 : 3;
    size_t smem = (size_t)NSTAGE * NBUF * 128 * 72 * sizeof(h16);
    if (HOUT && smem < 128 * 132 * sizeof(float)) smem = 128 * 132 * sizeof(float);
    cudaFuncSetAttribute(gemmH<TA, TB, CSKIP, KLIM, HOUT>,
                         cudaFuncAttributeMaxDynamicSharedMemorySize, (int)smem);
    dim3 grid(N / 128, M / 128, batch);
    gemmH<TA, TB, CSKIP, KLIM, HOUT><<<grid, 256, smem>>>(Ah, Al, Bh, Bl, C,
                                                          K, lda, ldb, ldc, sA, sB, sC);
}

// ---------------- split fp32 -> fp16 hi (+ optional lo) ------------------------
template <bool LO>
__global__ void split_kernel(const float4* __restrict__ src,
                             __half2* __restrict__ h,
                             __half2* __restrict__ l, int n4)
{
    int i = blockIdx.x * blockDim.x + threadIdx.x;
    if (i >= n4) return;
    float4 v = src[i];
    h16 h0 = __float2half_rn(v.x), h1 = __float2half_rn(v.y);
    h16 h2 = __float2half_rn(v.z), h3 = __float2half_rn(v.w);
    h[2*i]   = __halves2half2(h0, h1);
    h[2*i+1] = __halves2half2(h2, h3);
    if (LO) {
        h16 l0 = __float2half_rn(v.x - __half2float(h0));
        h16 l1 = __float2half_rn(v.y - __half2float(h1));
        h16 l2 = __float2half_rn(v.z - __half2float(h2));
        h16 l3 = __float2half_rn(v.w - __half2float(h3));
        l[2*i]   = __halves2half2(l0, l1);
        l[2*i+1] = __halves2half2(l2, l3);
    }
}
template <bool LO>
static void split(const float* src, h16* h, h16* l, long long n)
{
    int n4 = (int)(n / 4);
    split_kernel<LO><<<(n4 + 255) / 256, 256>>>((const float4*)src,
                                                (__half2*)h, (__half2*)l, n4);
}

// ---------------- transpose + convert: src[R][C] (T) -> dst[C][R] fp16 ----------
template <typename T>
__global__ void tconv_kernel(const T* __restrict__ src, int ld_src,
                             h16* __restrict__ dh,
                             int ld_dst, long long sSrc, long long sDst)
{
    __shared__ float t[32][33];
    const T* s = src + (long long)blockIdx.z * sSrc;
    h16* oh = dh + (long long)blockIdx.z * sDst;
    int r0 = blockIdx.x * 32;
    int c0 = blockIdx.y * 32;
    int tx = threadIdx.x, ty = threadIdx.y;
    #pragma unroll
    for (int j = 0; j < 4; j++)
        t[ty + j * 8][tx] = (float)s[(long long)(r0 + ty + j * 8) * ld_src + c0 + tx];
    __syncthreads();
    #pragma unroll
    for (int j = 0; j < 4; j++) {
        float v = t[tx][ty + j * 8];
        long long o = (long long)(c0 + ty + j * 8) * ld_dst + r0 + tx;
        oh[o] = __float2half_rn(v);
    }
}
template <typename T>
static void tconv(const T* src, int R, int Cc, int ld_src,
                  h16* dh, int ld_dst, long long sSrc, long long sDst, int batch)
{
    dim3 grid(R / 32, Cc / 32, batch), block(32, 8);
    tconv_kernel<T><<<grid, block>>>(src, ld_src, dh, ld_dst, sSrc, sDst);
}

// ---------------- rmsnorm over sum of two split-K partials (writes buf0) -------
__global__ void rmsnorm2_kernel(float* __restrict__ x0, const float* __restrict__ x1,
                                const float* __restrict__ w, int len, int stride)
{
    float* row0 = x0 + (long long)blockIdx.x * stride;
    const float* row1 = x1 + (long long)blockIdx.x * stride;
    __shared__ float red[256];
    int tid = threadIdx.x;
    float ss = 0.f;
    for (int j = tid; j < len; j += 256) { float v = row0[j] + row1[j]; ss += v * v; }
    red[tid] = ss; __syncthreads();
    for (int s = 128; s > 0; s >>= 1) {
        if (tid < s) red[tid] += red[tid + s];
        __syncthreads();
    }
    float rr = rsqrtf(red[0] / (float)len + 1e-6f);
    for (int j = tid; j < len; j += 256) row0[j] = (row0[j] + row1[j]) * rr * w[j];
}

// ---------------- RoPE ----------------------------------------------------------
// q in fp16 [s][h*192], rope dims 128..191, in place (fp32 math)
__global__ void rope_q16_kernel(h16* __restrict__ q)
{
    int idx = blockIdx.x * blockDim.x + threadIdx.x;
    if (idx >= SQ * NH * 32) return;
    int dp = idx & 31;
    int h  = (idx >> 5) & 127;
    int s  = idx >> 12;
    float a = (float)s * __expf(-(float)dp * (logf(10000.f) / 32.f));
    float c, sn;
    sincosf(a, &sn, &c);
    h16* base = q + (long long)s * (NH * DQ) + h * DQ + DN;
    float x1 = __half2float(base[dp]), x2 = __half2float(base[dp + 32]);
    base[dp]      = __float2half_rn(x1 * c - x2 * sn);
    base[dp + 32] = __float2half_rn(x2 * c + x1 * sn);
}
// k_pe from sum of two split-K partials (pre-norm cols), stride DPN
__global__ void rope_kpe2_kernel(const float* __restrict__ a0,
                                 const float* __restrict__ a1,
                                 int stride, float* __restrict__ kpe)
{
    int idx = blockIdx.x * blockDim.x + threadIdx.x;
    if (idx >= SQ * 32) return;
    int dp = idx & 31;
    int s  = idx >> 5;
    float a = (float)s * __expf(-(float)dp * (logf(10000.f) / 32.f));
    float c, sn;
    sincosf(a, &sn, &c);
    long long o = (long long)s * stride;
    float x1 = a0[o + dp]      + a1[o + dp];
    float x2 = a0[o + dp + 32] + a1[o + dp + 32];
    kpe[s * DR + dp]      = x1 * c - x2 * sn;
    kpe[s * DR + dp + 32] = x2 * c + x1 * sn;
}

// ---------------- assemble K_full from fp16 kv + fp32 kpe ----------------------
__global__ void assemble_k16_kernel(const h16* __restrict__ kv,
                                    const float* __restrict__ kpe,
                                    h16* __restrict__ kh)
{
    long long idx = (long long)blockIdx.x * blockDim.x + threadIdx.x;
    if (idx >= (long long)NH * SQ * DQ) return;
    int d = (int)(idx % DQ);
    int j = (int)((idx / DQ) % SQ);
    int h = (int)(idx / ((long long)DQ * SQ));
    if (d < DN) kh[idx] = kv[(long long)j * (NH * 256) + h * 256 + d];
    else        kh[idx] = __float2half_rn(kpe[j * DR + (d - DN)]);
}

// ---------------- causal softmax, fp16 in-place (scores -> P) ------------------
__global__ void softmax_p_kernel(h16* __restrict__ S)
{
    int r = blockIdx.x;                 // h*1024 + i
    int i = r & (SQ - 1);
    h16* row = S + (long long)r * SQ;
    const float scale = 0.07216878365f; // 1/sqrt(192)
    const int jmax = ((i >> 7) + 1) << 7;  // PV reads k < this bound
    int tid = threadIdx.x;
    int lane = tid & 31, warp = tid >> 5;
    __shared__ float redm[8], reds[8];

    float v[4];
    #pragma unroll
    for (int t = 0; t < 4; t++) {
        int j = tid + t * 256;
        v[t] = (j <= i) ? __half2float(row[j]) * scale : -FLT_MAX;
    }
    float mx = fmaxf(fmaxf(v[0], v[1]), fmaxf(v[2], v[3]));
    #pragma unroll
    for (int o = 16; o > 0; o >>= 1) mx = fmaxf(mx, __shfl_xor_sync(~0u, mx, o));
    if (lane == 0) redm[warp] = mx;
    __syncthreads();
    mx = redm[0];
    #pragma unroll
    for (int w = 1; w < 8; w++) mx = fmaxf(mx, redm[w]);

    float e[4];
    float sum = 0.f;
    #pragma unroll
    for (int t = 0; t < 4; t++) {
        int j = tid + t * 256;
        e[t] = (j <= i) ? __expf(v[t] - mx) : 0.f;
        sum += e[t];
    }
    #pragma unroll
    for (int o = 16; o > 0; o >>= 1) sum += __shfl_xor_sync(~0u, sum, o);
    if (lane == 0) reds[warp] = sum;
    __syncthreads();
    sum = 0.f;
    #pragma unroll
    for (int w = 0; w < 8; w++) sum += reds[w];
    float inv = 1.f / sum;

    #pragma unroll
    for (int t = 0; t < 4; t++) {
        int j = tid + t * 256;
        if (j < jmax) row[j] = __float2half_rn(e[t] * inv);
    }
}

// ---------------- host side -----------------------------------------------------
extern "C" void kernel_launch(void* const* d_in, const int* in_sizes, int n_in,
                              void* d_out, int out_size)
{
    const float* x     = (const float*)d_in[0];
    const float* Wqa   = (const float*)d_in[2];   // [7168,1536]
    const float* wqln  = (const float*)d_in[3];
    const float* Wqb   = (const float*)d_in[4];   // [1536,24576]
    const float* Wkva  = (const float*)d_in[5];   // [7168,576]
    const float* wkvln = (const float*)d_in[6];
    const float* Wkvb  = (const float*)d_in[7];   // [512,32768]
    const float* Wo    = (const float*)d_in[8];   // [16384,7168]
    float*       out   = (float*)d_out;

    float *qkva, *kpe;
    cudaGetSymbolAddress((void**)&qkva, g_qkva);
    cudaGetSymbolAddress((void**)&kpe,  g_kpe);
    float* qkva1 = qkva + (long long)SQ * DPN;   // second split-K partial

    h16 *xh,*xl,*qkvah,*q16,*kv16,*kh,*Phb,*aoh;
    h16 *Wdt_h,*Wqbt_h,*Wkvbt_h,*Wot_h,*Vt_h;
    cudaGetSymbolAddress((void**)&xh,    g_xh);    cudaGetSymbolAddress((void**)&xl,    g_xl);
    cudaGetSymbolAddress((void**)&qkvah, g_qkvah);
    cudaGetSymbolAddress((void**)&q16,   g_q16);
    cudaGetSymbolAddress((void**)&kv16,  g_kv16);
    cudaGetSymbolAddress((void**)&kh,    g_kh);
    cudaGetSymbolAddress((void**)&Phb,   g_Ph);
    cudaGetSymbolAddress((void**)&aoh,   g_aoh);
    cudaGetSymbolAddress((void**)&Wdt_h, g_Wdt_h);
    cudaGetSymbolAddress((void**)&Wqbt_h,  g_Wqb_t_h);
    cudaGetSymbolAddress((void**)&Wkvbt_h, g_Wkvb_t_h);
    cudaGetSymbolAddress((void**)&Wot_h,   g_Wo_t_h);
    cudaGetSymbolAddress((void**)&Vt_h,    g_Vt_h);

    // 0) split x (hi+lo); transpose+convert weights into [N][K] K-major fp16
    split<true>(x, xh, xl, (long long)SQ * HID);
    tconv<float>(Wqa,  HID,    QLORA,    QLORA,    Wdt_h,                        HID,    0, 0, 1);
    tconv<float>(Wkva, HID,    576,      576,      Wdt_h + (long long)QLORA*HID, HID,    0, 0, 1);
    tconv<float>(Wqb,  QLORA,  NH * DQ,  NH * DQ,  Wqbt_h,  QLORA,  0, 0, 1);
    tconv<float>(Wkvb, KVLORA, NH * 256, NH * 256, Wkvbt_h, KVLORA, 0, 0, 1);
    tconv<float>(Wo,   NH*DV,  HID,      HID,      Wot_h,   NH*DV,  0, 0, 1);

    // 1) combined down-projection (2,1), split-K=2 via batch axis (272 CTAs)
    rung<2,1,false,false,false>(xh, xl, Wdt_h, Wdt_h, qkva,
        SQ, DPN, HID / 2, HID, HID, DPN,
        HID / 2, HID / 2, (long long)SQ * DPN, 2);

    // 2) k_pe rope from partial sums; rmsnorms over partial sums (write buf0)
    rope_kpe2_kernel<<<(SQ * 32 + 255) / 256, 256>>>(
        qkva + QLORA + KVLORA, qkva1 + QLORA + KVLORA, DPN, kpe);
    rmsnorm2_kernel<<<SQ, 256>>>(qkva,         qkva1,         wqln,  QLORA,  DPN);
    rmsnorm2_kernel<<<SQ, 256>>>(qkva + QLORA, qkva1 + QLORA, wkvln, KVLORA, DPN);

    // 3) convert activations; up-projections (1,1) with fp16 output, 3-stage
    split<false>(qkva, qkvah, qkvah, (long long)SQ * DPN);
    rung<1,1,false,false,true>(qkvah, qkvah, Wqbt_h, Wqbt_h, (float*)q16,
        SQ, NH * DQ, QLORA, DPN, QLORA, NH * DQ, 0, 0, 0, 1);
    rung<1,1,false,false,true>(qkvah + QLORA, qkvah + QLORA, Wkvbt_h, Wkvbt_h, (float*)kv16,
        SQ, NH * 256, KVLORA, DPN, KVLORA, NH * 256, 0, 0, 0, 1);

    // 4) RoPE on fp16 q (in place); K assembly + V transpose from fp16 kv
    rope_q16_kernel<<<(SQ * NH * 32 + 255) / 256, 256>>>(q16);
    assemble_k16_kernel<<<(int)(((long long)NH * SQ * DQ + 255) / 256), 256>>>(kv16, kpe, kh);
    tconv<h16>(kv16 + DN, SQ, DV, NH * 256, Vt_h, SQ, 256, (long long)DV * SQ, NH);

    // 5) scores = Q @ K^T (1,1), causal tile-skip, fp16 out into P buffer
    rung<1,1,true,false,true>(q16, q16, kh, kh, (float*)Phb,
        SQ, SQ, DQ, NH * DQ, DQ, SQ,
        DQ, (long long)SQ * DQ, (long long)SQ * SQ, NH);

    // 6) causal softmax, fp16 in-place (scores -> P)
    softmax_p_kernel<<<NH * SQ, 256>>>(Phb);

    // 7) out_h = P @ V (1,1), k-limited, fp16 out -> aoh
    rung<1,1,false,true,true>(Phb, Phb, Vt_h, Vt_h, (float*)aoh,
        SQ, DV, SQ, SQ, SQ, NH * DV,
        (long long)SQ * SQ, (long long)DV * SQ, DV, NH);

    // 8) output projection (1,1), occ2, 3-stage
    rung<1,1,false,false,false>(aoh, aoh, Wot_h, Wot_h, out,
        SQ, HID, NH * DV, NH * DV, NH * DV, HID, 0, 0, 0, 1);
}

// round 14
// speedup vs baseline: 1.4315x; 1.0402x over previous
#include <cuda_runtime.h>
#include <cuda_fp16.h>
#include <mma.h>
#include <cfloat>
#include <cstdint>
#include <math.h>
#include <type_traits>

using namespace nvcuda;
typedef __half h16;

#define SQ   1024
#define NH   128
#define DQ   192
#define DN   128
#define DR   64
#define DV   128
#define HID  7168
#define QLORA 1536
#define KVLORA 512
#define KVAP 640            // padded kv_a width (576 -> 640)
#define DPN  (QLORA + KVAP) // combined down-proj width = 2176 (17 * 128)

// ---------------- scratch (device globals; allocation-free rule) -------------
__device__ float g_qkva[2 * SQ * DPN];    // split-K partials: [qa|kva] x2
__device__ float g_kpe[SQ * DR];

// fp16 activations
__device__ h16 g_xh[SQ * HID],  g_xl[SQ * HID];
__device__ h16 g_qkvah[SQ * DPN];
__device__ h16 g_q16[SQ * NH * DQ];             // q_b output (fp16), roped in place
__device__ h16 g_kv16[SQ * NH * 256];           // kv_b output (fp16)
__device__ h16 g_kh[(long long)NH * SQ * DQ];
__device__ h16 g_Ph[(long long)NH * SQ * SQ];   // scores (unscaled) then P, in-place
__device__ h16 g_aoh[SQ * NH * DV];             // attn out, fp16

// fp16 weights
__device__ h16 g_Wdt_h[(long long)DPN * HID];        // [Wqa|Wkva]^T, [N][K] K-major
__device__ h16 g_Wqb16[(long long)QLORA * NH * DQ];  // native [K][N]
__device__ h16 g_Wkvb16[(long long)KVLORA * NH * 256];
__device__ h16 g_Wo16[(long long)NH * DV * HID];

// ---------------- helpers -----------------------------------------------------
__device__ __forceinline__ void cp16(const h16* smem_dst, const h16* gsrc) {
    unsigned int saddr = (unsigned int)__cvta_generic_to_shared(smem_dst);
    asm volatile("cp.async.cg.shared.global [%0], [%1], 16;\n" :: "r"(saddr), "l"(gsrc));
}

// ---------------- mixed-term fp16 GEMM -----------------------------------------
// C[M,N] = A[M,K] @ B  (A K-major [M][K]; batch via blockIdx.z)
// BKN=false: B is [N][K] K-major (B^T form).  BKN=true: B is [K][N] row-major.
// Terms: Ah*Bh  (+ Al*Bh if TA==2)  (+ Ah*Bl if TB==2; only with BKN=false)
// HOUT: write fp16 (via smem staging) instead of fp32.
template <int TA, int TB, bool BKN, bool CSKIP, bool KLIM, bool HOUT>
__global__ void __launch_bounds__(256, 2)
gemmH(const h16* __restrict__ Ah, const h16* __restrict__ Al,
      const h16* __restrict__ Bh, const h16* __restrict__ Bl,
      float* __restrict__ C, int K, int lda, int ldb, int ldc,
      long long sA, long long sB, long long sC)
{
    constexpr int PITCHA = 72;            // 64 + 8 pad
    constexpr int ABUF   = 128 * PITCHA;
    constexpr int PITCHB = BKN ? 136 : 72;
    constexpr int BBUF   = (BKN ? 64 : 128) * PITCHB;
    constexpr int NBUF   = TA + TB;
    constexpr int NSTAGE = (NBUF == 3) ? 2 : 3;
    constexpr int STAGE  = TA * ABUF + TB * BBUF;
    using BLay = typename std::conditional<BKN, wmma::row_major, wmma::col_major>::type;

    const int m0 = blockIdx.y << 7, n0 = blockIdx.x << 7;
    if (CSKIP && n0 >= m0 + 128) return;
    const int b = blockIdx.z;
    Ah += (long long)b * sA;
    if (TA == 2) Al += (long long)b * sA;
    Bh += (long long)b * sB;
    if (TB == 2) Bl += (long long)b * sB;
    const long long coff = (long long)b * sC;
    const int Kend = KLIM ? ((m0 + 128 < K) ? m0 + 128 : K) : K;
    const int nK = Kend >> 6;

    extern __shared__ h16 sm[];
    const int tid = threadIdx.x, wid = tid >> 5;
    const int wm = (wid & 3) << 5;
    const int wn = (wid >> 2) << 6;

    auto load_stage = [&](int st, int kc) {
        const int k0 = kc << 6;
        h16* base = sm + st * STAGE;
        #pragma unroll
        for (int i = 0; i < NBUF * 4; i++) {
            int c   = tid + (i << 8);
            int buf = c >> 10;
            int w   = c & 1023;
            h16* dst;
            const h16* g;
            if (buf < TA) {
                int r = w >> 3, k8 = (w & 7) << 3;
                dst = base + buf * ABUF + r * PITCHA + k8;
                g = (buf == 0 ? Ah : Al) + (long long)(m0 + r) * lda + k0 + k8;
            } else {
                const h16* Bsrc = (buf == TA) ? Bh : Bl;
                h16* bb = base + TA * ABUF + (buf - TA) * BBUF;
                if (BKN) {
                    int r = w >> 4, n16 = (w & 15) << 3;   // 64 k-rows x 128 n-cols
                    dst = bb + r * PITCHB + n16;
                    g = Bsrc + (long long)(k0 + r) * ldb + n0 + n16;
                } else {
                    int r = w >> 3, k8 = (w & 7) << 3;     // 128 n-rows x 64 k-cols
                    dst = bb + r * PITCHB + k8;
                    g = Bsrc + (long long)(n0 + r) * ldb + k0 + k8;
                }
            }
            cp16(dst, g);
        }
        asm volatile("cp.async.commit_group;");
    };

    wmma::fragment<wmma::accumulator, 16, 16, 16, float> acc[2][4];
    #pragma unroll
    for (int i = 0; i < 2; i++)
        #pragma unroll
        for (int j = 0; j < 4; j++)
            wmma::fill_fragment(acc[i][j], 0.0f);

    auto compute = [&](int st) {
        const h16* base = sm + st * STAGE;
        const h16* sAh_ = base;
        const h16* sAl_ = base + ABUF;                // valid iff TA==2
        const h16* sBh_ = base + TA * ABUF;
        const h16* sBl_ = base + TA * ABUF + BBUF;    // valid iff TB==2
        #pragma unroll
        for (int kk = 0; kk < 4; kk++) {
            const int ko = kk << 4;
            wmma::fragment<wmma::matrix_a, 16, 16, 16, h16, wmma::row_major> ah[2], al[2];
            #pragma unroll
            for (int i = 0; i < 2; i++) {
                wmma::load_matrix_sync(ah[i], sAh_ + (wm + (i << 4)) * PITCHA + ko, PITCHA);
                if (TA == 2)
                    wmma::load_matrix_sync(al[i], sAl_ + (wm + (i << 4)) * PITCHA + ko, PITCHA);
            }
            #pragma unroll
            for (int j = 0; j < 4; j++) {
                wmma::fragment<wmma::matrix_b, 16, 16, 16, h16, BLay> bf;
                const h16* baddr = BKN ? (sBh_ + ko * PITCHB + wn + (j << 4))
                                       : (sBh_ + (wn + (j << 4)) * PITCHB + ko);
                wmma::load_matrix_sync(bf, baddr, PITCHB);
                #pragma unroll
                for (int i = 0; i < 2; i++) {
                    wmma::mma_sync(acc[i][j], ah[i], bf, acc[i][j]);
                    if (TA == 2) wmma::mma_sync(acc[i][j], al[i], bf, acc[i][j]);
                }
                if (TB == 2) {
                    const h16* baddr2 = BKN ? (sBl_ + ko * PITCHB + wn + (j << 4))
                                            : (sBl_ + (wn + (j << 4)) * PITCHB + ko);
                    wmma::load_matrix_sync(bf, baddr2, PITCHB);
                    #pragma unroll
                    for (int i = 0; i < 2; i++)
                        wmma::mma_sync(acc[i][j], ah[i], bf, acc[i][j]);
                }
            }
        }
    };

    if (NSTAGE == 2) {
        load_stage(0, 0);
        for (int kt = 0; kt < nK; kt++) {
            if (kt + 1 < nK) {
                load_stage((kt + 1) & 1, kt + 1);
                asm volatile("cp.async.wait_group 1;");
            } else {
                asm volatile("cp.async.wait_group 0;");
            }
            __syncthreads();
            compute(kt & 1);
            __syncthreads();
        }
    } else {
        load_stage(0, 0);
        if (nK > 1) load_stage(1, 1);
        for (int kt = 0; kt < nK; kt++) {
            if (kt + 2 < nK) {
                load_stage((kt + 2) % 3, kt + 2);
                asm volatile("cp.async.wait_group 2;");
            } else if (kt + 1 < nK) {
                asm volatile("cp.async.wait_group 1;");
            } else {
                asm volatile("cp.async.wait_group 0;");
            }
            __syncthreads();
            compute(kt % 3);
            __syncthreads();
        }
    }

    if (!HOUT) {
        float* Cf = C + coff;
        #pragma unroll
        for (int i = 0; i < 2; i++)
            #pragma unroll
            for (int j = 0; j < 4; j++)
                wmma::store_matrix_sync(
                    &Cf[(long long)(m0 + wm + (i << 4)) * ldc + n0 + wn + (j << 4)],
                    acc[i][j], ldc, wmma::mem_row_major);
    } else {
        float* smf = (float*)sm;   // 128 x 132 floats = 67584 B <= stage smem
        #pragma unroll
        for (int i = 0; i < 2; i++)
            #pragma unroll
            for (int j = 0; j < 4; j++)
                wmma::store_matrix_sync(
                    &smf[(wm + (i << 4)) * 132 + wn + (j << 4)],
                    acc[i][j], 132, wmma::mem_row_major);
        __syncthreads();
        h16* Ch = (h16*)C + coff;
        #pragma unroll
        for (int it = 0; it < 64; it++) {
            int idx = tid + (it << 8);
            int m = idx >> 7, n = idx & 127;
            Ch[(long long)(m0 + m) * ldc + n0 + n] = __float2half_rn(smf[m * 132 + n]);
        }
    }
}

template <int TA, int TB, bool BKN, bool CSKIP, bool KLIM, bool HOUT>
static void rung(const h16* Ah, const h16* Al, const h16* Bh, const h16* Bl,
                 float* C, int M, int N, int K, int lda, int ldb, int ldc,
                 long long sA, long long sB, long long sC, int batch)
{
    constexpr int ABUF   = 128 * 72;
    constexpr int BBUF   = (BKN ? 64 : 128) * (BKN ? 136 : 72);
    constexpr int NBUF   = TA + TB;
    constexpr int NSTAGE = (NBUF == 3) ? 2 : 3;
    size_t smem = (size_t)NSTAGE * (TA * ABUF + TB * BBUF) * sizeof(h16);
    if (HOUT && smem < 128 * 132 * sizeof(float)) smem = 128 * 132 * sizeof(float);
    cudaFuncSetAttribute(gemmH<TA, TB, BKN, CSKIP, KLIM, HOUT>,
                         cudaFuncAttributeMaxDynamicSharedMemorySize, (int)smem);
    dim3 grid(N / 128, M / 128, batch);
    gemmH<TA, TB, BKN, CSKIP, KLIM, HOUT><<<grid, 256, smem>>>(Ah, Al, Bh, Bl, C,
                                                               K, lda, ldb, ldc, sA, sB, sC);
}

// ---------------- split fp32 -> fp16 hi (+ optional lo) ------------------------
template <bool LO>
__global__ void split_kernel(const float4* __restrict__ src,
                             __half2* __restrict__ h,
                             __half2* __restrict__ l, int n4)
{
    int i = blockIdx.x * blockDim.x + threadIdx.x;
    if (i >= n4) return;
    float4 v = src[i];
    h16 h0 = __float2half_rn(v.x), h1 = __float2half_rn(v.y);
    h16 h2 = __float2half_rn(v.z), h3 = __float2half_rn(v.w);
    h[2*i]   = __halves2half2(h0, h1);
    h[2*i+1] = __halves2half2(h2, h3);
    if (LO) {
        h16 l0 = __float2half_rn(v.x - __half2float(h0));
        h16 l1 = __float2half_rn(v.y - __half2float(h1));
        h16 l2 = __float2half_rn(v.z - __half2float(h2));
        h16 l3 = __float2half_rn(v.w - __half2float(h3));
        l[2*i]   = __halves2half2(l0, l1);
        l[2*i+1] = __halves2half2(l2, l3);
    }
}
template <bool LO>
static void split(const float* src, h16* h, h16* l, long long n)
{
    int n4 = (int)(n / 4);
    split_kernel<LO><<<(n4 + 255) / 256, 256>>>((const float4*)src,
                                                (__half2*)h, (__half2*)l, n4);
}

// ---------------- transpose + convert: src[R][C] fp32 -> dst[C][R] fp16 --------
__global__ void tconv_kernel(const float* __restrict__ src, int ld_src,
                             h16* __restrict__ dh, int ld_dst)
{
    __shared__ float t[32][33];
    int r0 = blockIdx.x * 32;
    int c0 = blockIdx.y * 32;
    int tx = threadIdx.x, ty = threadIdx.y;
    #pragma unroll
    for (int j = 0; j < 4; j++)
        t[ty + j * 8][tx] = src[(long long)(r0 + ty + j * 8) * ld_src + c0 + tx];
    __syncthreads();
    #pragma unroll
    for (int j = 0; j < 4; j++) {
        float v = t[tx][ty + j * 8];
        dh[(long long)(c0 + ty + j * 8) * ld_dst + r0 + tx] = __float2half_rn(v);
    }
}
static void tconv(const float* src, int R, int Cc, int ld_src, h16* dh, int ld_dst)
{
    dim3 grid(R / 32, Cc / 32), block(32, 8);
    tconv_kernel<<<grid, block>>>(src, ld_src, dh, ld_dst);
}

// ---------------- rmsnorm over sum of two split-K partials (writes buf0) -------
__global__ void rmsnorm2_kernel(float* __restrict__ x0, const float* __restrict__ x1,
                                const float* __restrict__ w, int len, int stride)
{
    float* row0 = x0 + (long long)blockIdx.x * stride;
    const float* row1 = x1 + (long long)blockIdx.x * stride;
    __shared__ float red[256];
    int tid = threadIdx.x;
    float ss = 0.f;
    for (int j = tid; j < len; j += 256) { float v = row0[j] + row1[j]; ss += v * v; }
    red[tid] = ss; __syncthreads();
    for (int s = 128; s > 0; s >>= 1) {
        if (tid < s) red[tid] += red[tid + s];
        __syncthreads();
    }
    float rr = rsqrtf(red[0] / (float)len + 1e-6f);
    for (int j = tid; j < len; j += 256) row0[j] = (row0[j] + row1[j]) * rr * w[j];
}

// ---------------- RoPE ----------------------------------------------------------
__global__ void rope_q16_kernel(h16* __restrict__ q)
{
    int idx = blockIdx.x * blockDim.x + threadIdx.x;
    if (idx >= SQ * NH * 32) return;
    int dp = idx & 31;
    int h  = (idx >> 5) & 127;
    int s  = idx >> 12;
    float a = (float)s * __expf(-(float)dp * (logf(10000.f) / 32.f));
    float c, sn;
    sincosf(a, &sn, &c);
    h16* base = q + (long long)s * (NH * DQ) + h * DQ + DN;
    float x1 = __half2float(base[dp]), x2 = __half2float(base[dp + 32]);
    base[dp]      = __float2half_rn(x1 * c - x2 * sn);
    base[dp + 32] = __float2half_rn(x2 * c + x1 * sn);
}
__global__ void rope_kpe2_kernel(const float* __restrict__ a0,
                                 const float* __restrict__ a1,
                                 int stride, float* __restrict__ kpe)
{
    int idx = blockIdx.x * blockDim.x + threadIdx.x;
    if (idx >= SQ * 32) return;
    int dp = idx & 31;
    int s  = idx >> 5;
    float a = (float)s * __expf(-(float)dp * (logf(10000.f) / 32.f));
    float c, sn;
    sincosf(a, &sn, &c);
    long long o = (long long)s * stride;
    float x1 = a0[o + dp]      + a1[o + dp];
    float x2 = a0[o + dp + 32] + a1[o + dp + 32];
    kpe[s * DR + dp]      = x1 * c - x2 * sn;
    kpe[s * DR + dp + 32] = x2 * c + x1 * sn;
}

// ---------------- assemble K_full from fp16 kv + fp32 kpe ----------------------
__global__ void assemble_k16_kernel(const h16* __restrict__ kv,
                                    const float* __restrict__ kpe,
                                    h16* __restrict__ kh)
{
    long long idx = (long long)blockIdx.x * blockDim.x + threadIdx.x;
    if (idx >= (long long)NH * SQ * DQ) return;
    int d = (int)(idx % DQ);
    int j = (int)((idx / DQ) % SQ);
    int h = (int)(idx / ((long long)DQ * SQ));
    if (d < DN) kh[idx] = kv[(long long)j * (NH * 256) + h * 256 + d];
    else        kh[idx] = __float2half_rn(kpe[j * DR + (d - DN)]);
}

// ---------------- causal softmax, fp16 in-place (scores -> P) ------------------
__global__ void softmax_p_kernel(h16* __restrict__ S)
{
    int r = blockIdx.x;                 // h*1024 + i
    int i = r & (SQ - 1);
    h16* row = S + (long long)r * SQ;
    const float scale = 0.07216878365f; // 1/sqrt(192)
    const int jmax = ((i >> 7) + 1) << 7;  // PV reads k < this bound
    int tid = threadIdx.x;
    int lane = tid & 31, warp = tid >> 5;
    __shared__ float redm[8], reds[8];

    float v[4];
    #pragma unroll
    for (int t = 0; t < 4; t++) {
        int j = tid + t * 256;
        v[t] = (j <= i) ? __half2float(row[j]) * scale : -FLT_MAX;
    }
    float mx = fmaxf(fmaxf(v[0], v[1]), fmaxf(v[2], v[3]));
    #pragma unroll
    for (int o = 16; o > 0; o >>= 1) mx = fmaxf(mx, __shfl_xor_sync(~0u, mx, o));
    if (lane == 0) redm[warp] = mx;
    __syncthreads();
    mx = redm[0];
    #pragma unroll
    for (int w = 1; w < 8; w++) mx = fmaxf(mx, redm[w]);

    float e[4];
    float sum = 0.f;
    #pragma unroll
    for (int t = 0; t < 4; t++) {
        int j = tid + t * 256;
        e[t] = (j <= i) ? __expf(v[t] - mx) : 0.f;
        sum += e[t];
    }
    #pragma unroll
    for (int o = 16; o > 0; o >>= 1) sum += __shfl_xor_sync(~0u, sum, o);
    if (lane == 0) reds[warp] = sum;
    __syncthreads();
    sum = 0.f;
    #pragma unroll
    for (int w = 0; w < 8; w++) sum += reds[w];
    float inv = 1.f / sum;

    #pragma unroll
    for (int t = 0; t < 4; t++) {
        int j = tid + t * 256;
        if (j < jmax) row[j] = __float2half_rn(e[t] * inv);
    }
}

// ---------------- host side -----------------------------------------------------
extern "C" void kernel_launch(void* const* d_in, const int* in_sizes, int n_in,
                              void* d_out, int out_size)
{
    const float* x     = (const float*)d_in[0];
    const float* Wqa   = (const float*)d_in[2];   // [7168,1536]
    const float* wqln  = (const float*)d_in[3];
    const float* Wqb   = (const float*)d_in[4];   // [1536,24576]
    const float* Wkva  = (const float*)d_in[5];   // [7168,576]
    const float* wkvln = (const float*)d_in[6];
    const float* Wkvb  = (const float*)d_in[7];   // [512,32768]
    const float* Wo    = (const float*)d_in[8];   // [16384,7168]
    float*       out   = (float*)d_out;

    float *qkva, *kpe;
    cudaGetSymbolAddress((void**)&qkva, g_qkva);
    cudaGetSymbolAddress((void**)&kpe,  g_kpe);
    float* qkva1 = qkva + (long long)SQ * DPN;   // second split-K partial

    h16 *xh,*xl,*qkvah,*q16,*kv16,*kh,*Phb,*aoh;
    h16 *Wdt_h,*Wqb16,*Wkvb16,*Wo16;
    cudaGetSymbolAddress((void**)&xh,    g_xh);    cudaGetSymbolAddress((void**)&xl,    g_xl);
    cudaGetSymbolAddress((void**)&qkvah, g_qkvah);
    cudaGetSymbolAddress((void**)&q16,   g_q16);
    cudaGetSymbolAddress((void**)&kv16,  g_kv16);
    cudaGetSymbolAddress((void**)&kh,    g_kh);
    cudaGetSymbolAddress((void**)&Phb,   g_Ph);
    cudaGetSymbolAddress((void**)&aoh,   g_aoh);
    cudaGetSymbolAddress((void**)&Wdt_h,  g_Wdt_h);
    cudaGetSymbolAddress((void**)&Wqb16,  g_Wqb16);
    cudaGetSymbolAddress((void**)&Wkvb16, g_Wkvb16);
    cudaGetSymbolAddress((void**)&Wo16,   g_Wo16);

    // 0) split x (hi+lo); weight prep:
    //    Wqa/Wkva transposed into [N][K] (small); Wqb/Wkvb/Wo straight convert (native [K][N])
    split<true>(x, xh, xl, (long long)SQ * HID);
    tconv(Wqa,  HID, QLORA, QLORA, Wdt_h,                        HID);
    tconv(Wkva, HID, 576,   576,   Wdt_h + (long long)QLORA*HID, HID);
    split<false>(Wqb,  Wqb16,  Wqb16,  (long long)QLORA * NH * DQ);
    split<false>(Wkvb, Wkvb16, Wkvb16, (long long)KVLORA * NH * 256);
    split<false>(Wo,   Wo16,   Wo16,   (long long)NH * DV * HID);

    // 1) combined down-projection (2,1), split-K=2 via batch axis (272 CTAs)
    rung<2,1,false,false,false,false>(xh, xl, Wdt_h, Wdt_h, qkva,
        SQ, DPN, HID / 2, HID, HID, DPN,
        HID / 2, HID / 2, (long long)SQ * DPN, 2);

    // 2) k_pe rope from partial sums; rmsnorms over partial sums (write buf0)
    rope_kpe2_kernel<<<(SQ * 32 + 255) / 256, 256>>>(
        qkva + QLORA + KVLORA, qkva1 + QLORA + KVLORA, DPN, kpe);
    rmsnorm2_kernel<<<SQ, 256>>>(qkva,         qkva1,         wqln,  QLORA,  DPN);
    rmsnorm2_kernel<<<SQ, 256>>>(qkva + QLORA, qkva1 + QLORA, wkvln, KVLORA, DPN);

    // 3) convert activations; up-projections (1,1) BKN (native-layout weights), fp16 out
    split<false>(qkva, qkvah, qkvah, (long long)SQ * DPN);
    rung<1,1,true,false,false,true>(qkvah, qkvah, Wqb16, Wqb16, (float*)q16,
        SQ, NH * DQ, QLORA, DPN, NH * DQ, NH * DQ, 0, 0, 0, 1);
    rung<1,1,true,false,false,true>(qkvah + QLORA, qkvah + QLORA, Wkvb16, Wkvb16, (float*)kv16,
        SQ, NH * 256, KVLORA, DPN, NH * 256, NH * 256, 0, 0, 0, 1);

    // 4) RoPE on fp16 q (in place); K assembly (V read in place by PV)
    rope_q16_kernel<<<(SQ * NH * 32 + 255) / 256, 256>>>(q16);
    assemble_k16_kernel<<<(int)(((long long)NH * SQ * DQ + 255) / 256), 256>>>(kv16, kpe, kh);

    // 5) scores = Q @ K^T (1,1), B^T form, causal tile-skip, fp16 out into P buffer
    rung<1,1,false,true,false,true>(q16, q16, kh, kh, (float*)Phb,
        SQ, SQ, DQ, NH * DQ, DQ, SQ,
        DQ, (long long)SQ * DQ, (long long)SQ * SQ, NH);

    // 6) causal softmax, fp16 in-place (scores -> P)
    softmax_p_kernel<<<NH * SQ, 256>>>(Phb);

    // 7) out_h = P @ V (1,1) BKN: V read directly from kv16 (no transpose), k-limited
    rung<1,1,true,false,true,true>(Phb, Phb, kv16 + DN, kv16 + DN, (float*)aoh,
        SQ, DV, SQ, SQ, NH * 256, NH * DV,
        (long long)SQ * SQ, 256, DV, NH);

    // 8) output projection (1,1) BKN (native Wo layout), occ2
    rung<1,1,true,false,false,false>(aoh, aoh, Wo16, Wo16, out,
        SQ, HID, NH * DV, NH * DV, HID, HID, 0, 0, 0, 1);
}

// round 15
// speedup vs baseline: 1.4888x; 1.0401x over previous
#include <cuda_runtime.h>
#include <cuda_fp16.h>
#include <mma.h>
#include <cfloat>
#include <cstdint>
#include <math.h>
#include <type_traits>

using namespace nvcuda;
typedef __half h16;

#define SQ   1024
#define NH   128
#define DQ   192
#define DN   128
#define DR   64
#define DV   128
#define HID  7168
#define QLORA 1536
#define KVLORA 512
#define KVAP 640            // padded kv_a width (576 -> 640)
#define DPN  (QLORA + KVAP) // combined down-proj width = 2176 (17 * 128)

// ---------------- scratch (device globals; allocation-free rule) -------------
__device__ float g_qkva[2 * SQ * DPN];    // split-K partials: [qa|kva] x2

// fp16 activations
__device__ h16 g_xh[SQ * HID],  g_xl[SQ * HID];
__device__ h16 g_qkvah[SQ * DPN];
__device__ h16 g_q16[SQ * NH * DQ];             // q_b output (fp16), roped in place
__device__ h16 g_kv16[SQ * NH * 256];           // kv_b output (fp16)
__device__ h16 g_kpe16[SQ * DR];                // roped k_pe, fp16 (shared by all heads)
__device__ h16 g_Ph[(long long)NH * SQ * SQ];   // scores (unscaled) then P, in-place
__device__ h16 g_aoh[SQ * NH * DV];             // attn out, fp16

// fp16 weights
__device__ h16 g_Wdt_h[(long long)DPN * HID];        // [Wqa|Wkva]^T, [N][K] K-major
__device__ h16 g_Wqb16[(long long)QLORA * NH * DQ];  // native [K][N]
__device__ h16 g_Wkvb16[(long long)KVLORA * NH * 256];
__device__ h16 g_Wo16[(long long)NH * DV * HID];

// ---------------- helpers -----------------------------------------------------
__device__ __forceinline__ void cp16(const h16* smem_dst, const h16* gsrc) {
    unsigned int saddr = (unsigned int)__cvta_generic_to_shared(smem_dst);
    asm volatile("cp.async.cg.shared.global [%0], [%1], 16;\n" :: "r"(saddr), "l"(gsrc));
}

// ---------------- mixed-term fp16 GEMM -----------------------------------------
// C[M,N] = A[M,K] @ B  (A K-major [M][K]; batch via blockIdx.z)
// BKN=false: B is [N][K] K-major (B^T form).  BKN=true: B is [K][N] row-major.
// BSC: scores mode — B k-chunks 0,1 from Bh (kv16 view), chunk 2 from Bl (kpe16,
//      batch-invariant, ld=64). Only with BKN=false, TB==1, K==192.
// Terms: Ah*Bh  (+ Al*Bh if TA==2)  (+ Ah*Bl if TB==2; only with BKN=false, !BSC)
// HOUT: write fp16 (via smem staging). MX: map M to blockIdx.x (B-tile reuse).
template <int TA, int TB, bool BKN, bool BSC, bool CSKIP, bool KLIM, bool HOUT, bool MX>
__global__ void __launch_bounds__(256, 2)
gemmH(const h16* __restrict__ Ah, const h16* __restrict__ Al,
      const h16* __restrict__ Bh, const h16* __restrict__ Bl,
      float* __restrict__ C, int K, int lda, int ldb, int ldc,
      long long sA, long long sB, long long sC)
{
    constexpr int PITCHA = 72;            // 64 + 8 pad
    constexpr int ABUF   = 128 * PITCHA;
    constexpr int PITCHB = BKN ? 136 : 72;
    constexpr int BBUF   = (BKN ? 64 : 128) * PITCHB;
    constexpr int NBUF   = TA + TB;
    constexpr int NSTAGE = (NBUF == 3) ? 2 : 3;
    constexpr int STAGE  = TA * ABUF + TB * BBUF;
    using BLay = typename std::conditional<BKN, wmma::row_major, wmma::col_major>::type;

    const int m0 = (MX ? blockIdx.x : blockIdx.y) << 7;
    const int n0 = (MX ? blockIdx.y : blockIdx.x) << 7;
    if (CSKIP && n0 >= m0 + 128) return;
    const int b = blockIdx.z;
    Ah += (long long)b * sA;
    if (TA == 2) Al += (long long)b * sA;
    Bh += (long long)b * sB;
    if (TB == 2) Bl += (long long)b * sB;
    const long long coff = (long long)b * sC;
    const int Kend = KLIM ? ((m0 + 128 < K) ? m0 + 128 : K) : K;
    const int nK = Kend >> 6;

    extern __shared__ h16 sm[];
    const int tid = threadIdx.x, wid = tid >> 5;
    const int wm = (wid & 3) << 5;
    const int wn = (wid >> 2) << 6;

    auto load_stage = [&](int st, int kc) {
        const int k0 = kc << 6;
        h16* base = sm + st * STAGE;
        #pragma unroll
        for (int i = 0; i < NBUF * 4; i++) {
            int c   = tid + (i << 8);
            int buf = c >> 10;
            int w   = c & 1023;
            h16* dst;
            const h16* g;
            if (buf < TA) {
                int r = w >> 3, k8 = (w & 7) << 3;
                dst = base + buf * ABUF + r * PITCHA + k8;
                g = (buf == 0 ? Ah : Al) + (long long)(m0 + r) * lda + k0 + k8;
            } else {
                const h16* Bsrc = (buf == TA) ? Bh : Bl;
                h16* bb = base + TA * ABUF + (buf - TA) * BBUF;
                if (BKN) {
                    int r = w >> 4, n16 = (w & 15) << 3;   // 64 k-rows x 128 n-cols
                    dst = bb + r * PITCHB + n16;
                    g = Bsrc + (long long)(k0 + r) * ldb + n0 + n16;
                } else {
                    int r = w >> 3, k8 = (w & 7) << 3;     // 128 n-rows x 64 k-cols
                    dst = bb + r * PITCHB + k8;
                    if (BSC && k0 >= 128)
                        g = Bl + (long long)(n0 + r) * DR + (k0 - 128) + k8;  // kpe16, no batch
                    else
                        g = Bsrc + (long long)(n0 + r) * ldb + k0 + k8;
                }
            }
            cp16(dst, g);
        }
        asm volatile("cp.async.commit_group;");
    };

    wmma::fragment<wmma::accumulator, 16, 16, 16, float> acc[2][4];
    #pragma unroll
    for (int i = 0; i < 2; i++)
        #pragma unroll
        for (int j = 0; j < 4; j++)
            wmma::fill_fragment(acc[i][j], 0.0f);

    auto compute = [&](int st) {
        const h16* base = sm + st * STAGE;
        const h16* sAh_ = base;
        const h16* sAl_ = base + ABUF;                // valid iff TA==2
        const h16* sBh_ = base + TA * ABUF;
        const h16* sBl_ = base + TA * ABUF + BBUF;    // valid iff TB==2
        #pragma unroll
        for (int kk = 0; kk < 4; kk++) {
            const int ko = kk << 4;
            wmma::fragment<wmma::matrix_a, 16, 16, 16, h16, wmma::row_major> ah[2], al[2];
            #pragma unroll
            for (int i = 0; i < 2; i++) {
                wmma::load_matrix_sync(ah[i], sAh_ + (wm + (i << 4)) * PITCHA + ko, PITCHA);
                if (TA == 2)
                    wmma::load_matrix_sync(al[i], sAl_ + (wm + (i << 4)) * PITCHA + ko, PITCHA);
            }
            #pragma unroll
            for (int j = 0; j < 4; j++) {
                wmma::fragment<wmma::matrix_b, 16, 16, 16, h16, BLay> bf;
                const h16* baddr = BKN ? (sBh_ + ko * PITCHB + wn + (j << 4))
                                       : (sBh_ + (wn + (j << 4)) * PITCHB + ko);
                wmma::load_matrix_sync(bf, baddr, PITCHB);
                #pragma unroll
                for (int i = 0; i < 2; i++) {
                    wmma::mma_sync(acc[i][j], ah[i], bf, acc[i][j]);
                    if (TA == 2) wmma::mma_sync(acc[i][j], al[i], bf, acc[i][j]);
                }
                if (TB == 2) {
                    const h16* baddr2 = BKN ? (sBl_ + ko * PITCHB + wn + (j << 4))
                                            : (sBl_ + (wn + (j << 4)) * PITCHB + ko);
                    wmma::load_matrix_sync(bf, baddr2, PITCHB);
                    #pragma unroll
                    for (int i = 0; i < 2; i++)
                        wmma::mma_sync(acc[i][j], ah[i], bf, acc[i][j]);
                }
            }
        }
    };

    if (NSTAGE == 2) {
        load_stage(0, 0);
        for (int kt = 0; kt < nK; kt++) {
            if (kt + 1 < nK) {
                load_stage((kt + 1) & 1, kt + 1);
                asm volatile("cp.async.wait_group 1;");
            } else {
                asm volatile("cp.async.wait_group 0;");
            }
            __syncthreads();
            compute(kt & 1);
            __syncthreads();
        }
    } else {
        load_stage(0, 0);
        if (nK > 1) load_stage(1, 1);
        for (int kt = 0; kt < nK; kt++) {
            if (kt + 2 < nK) {
                load_stage((kt + 2) % 3, kt + 2);
                asm volatile("cp.async.wait_group 2;");
            } else if (kt + 1 < nK) {
                asm volatile("cp.async.wait_group 1;");
            } else {
                asm volatile("cp.async.wait_group 0;");
            }
            __syncthreads();
            compute(kt % 3);
            __syncthreads();
        }
    }

    if (!HOUT) {
        float* Cf = C + coff;
        #pragma unroll
        for (int i = 0; i < 2; i++)
            #pragma unroll
            for (int j = 0; j < 4; j++)
                wmma::store_matrix_sync(
                    &Cf[(long long)(m0 + wm + (i << 4)) * ldc + n0 + wn + (j << 4)],
                    acc[i][j], ldc, wmma::mem_row_major);
    } else {
        float* smf = (float*)sm;   // 128 x 132 floats = 67584 B <= stage smem
        #pragma unroll
        for (int i = 0; i < 2; i++)
            #pragma unroll
            for (int j = 0; j < 4; j++)
                wmma::store_matrix_sync(
                    &smf[(wm + (i << 4)) * 132 + wn + (j << 4)],
                    acc[i][j], 132, wmma::mem_row_major);
        __syncthreads();
        h16* Ch = (h16*)C + coff;
        #pragma unroll
        for (int it = 0; it < 64; it++) {
            int idx = tid + (it << 8);
            int m = idx >> 7, n = idx & 127;
            Ch[(long long)(m0 + m) * ldc + n0 + n] = __float2half_rn(smf[m * 132 + n]);
        }
    }
}

template <int TA, int TB, bool BKN, bool BSC, bool CSKIP, bool KLIM, bool HOUT, bool MX>
static void rung(const h16* Ah, const h16* Al, const h16* Bh, const h16* Bl,
                 float* C, int M, int N, int K, int lda, int ldb, int ldc,
                 long long sA, long long sB, long long sC, int batch)
{
    constexpr int ABUF   = 128 * 72;
    constexpr int BBUF   = (BKN ? 64 : 128) * (BKN ? 136 : 72);
    constexpr int NBUF   = TA + TB;
    constexpr int NSTAGE = (NBUF == 3) ? 2 : 3;
    size_t smem = (size_t)NSTAGE * (TA * ABUF + TB * BBUF) * sizeof(h16);
    if (HOUT && smem < 128 * 132 * sizeof(float)) smem = 128 * 132 * sizeof(float);
    cudaFuncSetAttribute(gemmH<TA, TB, BKN, BSC, CSKIP, KLIM, HOUT, MX>,
                         cudaFuncAttributeMaxDynamicSharedMemorySize, (int)smem);
    dim3 grid(MX ? M / 128 : N / 128, MX ? N / 128 : M / 128, batch);
    gemmH<TA, TB, BKN, BSC, CSKIP, KLIM, HOUT, MX><<<grid, 256, smem>>>(
        Ah, Al, Bh, Bl, C, K, lda, ldb, ldc, sA, sB, sC);
}

// ---------------- split fp32 -> fp16 hi (+ optional lo), 32B/thread ------------
template <bool LO>
__global__ void split_kernel(const float4* __restrict__ src,
                             __half2* __restrict__ h,
                             __half2* __restrict__ l, int n4)
{
    int i0 = (blockIdx.x * blockDim.x + threadIdx.x) * 2;
    #pragma unroll
    for (int u = 0; u < 2; u++) {
        int i = i0 + u;
        if (i >= n4) return;
        float4 v = src[i];
        h16 h0 = __float2half_rn(v.x), h1 = __float2half_rn(v.y);
        h16 h2 = __float2half_rn(v.z), h3 = __float2half_rn(v.w);
        h[2*i]   = __halves2half2(h0, h1);
        h[2*i+1] = __halves2half2(h2, h3);
        if (LO) {
            h16 l0 = __float2half_rn(v.x - __half2float(h0));
            h16 l1 = __float2half_rn(v.y - __half2float(h1));
            h16 l2 = __float2half_rn(v.z - __half2float(h2));
            h16 l3 = __float2half_rn(v.w - __half2float(h3));
            l[2*i]   = __halves2half2(l0, l1);
            l[2*i+1] = __halves2half2(l2, l3);
        }
    }
}
template <bool LO>
static void split(const float* src, h16* h, h16* l, long long n)
{
    int n4 = (int)(n / 4);
    int nthread = (n4 + 1) / 2;
    split_kernel<LO><<<(nthread + 255) / 256, 256>>>((const float4*)src,
                                                     (__half2*)h, (__half2*)l, n4);
}

// ---------------- transpose + convert: src[R][C] fp32 -> dst[C][R] fp16 --------
__global__ void tconv_kernel(const float* __restrict__ src, int ld_src,
                             h16* __restrict__ dh, int ld_dst)
{
    __shared__ float t[32][33];
    int r0 = blockIdx.x * 32;
    int c0 = blockIdx.y * 32;
    int tx = threadIdx.x, ty = threadIdx.y;
    #pragma unroll
    for (int j = 0; j < 4; j++)
        t[ty + j * 8][tx] = src[(long long)(r0 + ty + j * 8) * ld_src + c0 + tx];
    __syncthreads();
    #pragma unroll
    for (int j = 0; j < 4; j++) {
        float v = t[tx][ty + j * 8];
        dh[(long long)(c0 + ty + j * 8) * ld_dst + r0 + tx] = __float2half_rn(v);
    }
}
static void tconv(const float* src, int R, int Cc, int ld_src, h16* dh, int ld_dst)
{
    dim3 grid(R / 32, Cc / 32), block(32, 8);
    tconv_kernel<<<grid, block>>>(src, ld_src, dh, ld_dst);
}

// ---------------- rmsnorm over sum of two split-K partials (writes buf0) -------
__global__ void rmsnorm2_kernel(float* __restrict__ x0, const float* __restrict__ x1,
                                const float* __restrict__ w, int len, int stride)
{
    float* row0 = x0 + (long long)blockIdx.x * stride;
    const float* row1 = x1 + (long long)blockIdx.x * stride;
    __shared__ float red[256];
    int tid = threadIdx.x;
    float ss = 0.f;
    for (int j = tid; j < len; j += 256) { float v = row0[j] + row1[j]; ss += v * v; }
    red[tid] = ss; __syncthreads();
    for (int s = 128; s > 0; s >>= 1) {
        if (tid < s) red[tid] += red[tid + s];
        __syncthreads();
    }
    float rr = rsqrtf(red[0] / (float)len + 1e-6f);
    for (int j = tid; j < len; j += 256) row0[j] = (row0[j] + row1[j]) * rr * w[j];
}

// ---------------- RoPE ----------------------------------------------------------
__global__ void rope_q16_kernel(h16* __restrict__ q)
{
    int idx = blockIdx.x * blockDim.x + threadIdx.x;
    if (idx >= SQ * NH * 32) return;
    int dp = idx & 31;
    int h  = (idx >> 5) & 127;
    int s  = idx >> 12;
    float a = (float)s * __expf(-(float)dp * (logf(10000.f) / 32.f));
    float c, sn;
    sincosf(a, &sn, &c);
    h16* base = q + (long long)s * (NH * DQ) + h * DQ + DN;
    float x1 = __half2float(base[dp]), x2 = __half2float(base[dp + 32]);
    base[dp]      = __float2half_rn(x1 * c - x2 * sn);
    base[dp + 32] = __float2half_rn(x2 * c + x1 * sn);
}
// k_pe from sum of two split-K partials (pre-norm cols), fp16 output
__global__ void rope_kpe2_kernel(const float* __restrict__ a0,
                                 const float* __restrict__ a1,
                                 int stride, h16* __restrict__ kpe)
{
    int idx = blockIdx.x * blockDim.x + threadIdx.x;
    if (idx >= SQ * 32) return;
    int dp = idx & 31;
    int s  = idx >> 5;
    float a = (float)s * __expf(-(float)dp * (logf(10000.f) / 32.f));
    float c, sn;
    sincosf(a, &sn, &c);
    long long o = (long long)s * stride;
    float x1 = a0[o + dp]      + a1[o + dp];
    float x2 = a0[o + dp + 32] + a1[o + dp + 32];
    kpe[s * DR + dp]      = __float2half_rn(x1 * c - x2 * sn);
    kpe[s * DR + dp + 32] = __float2half_rn(x2 * c + x1 * sn);
}

// ---------------- causal softmax, fp16 in-place (scores -> P) ------------------
__global__ void softmax_p_kernel(h16* __restrict__ S)
{
    int r = blockIdx.x;                 // h*1024 + i
    int i = r & (SQ - 1);
    h16* row = S + (long long)r * SQ;
    const float scale = 0.07216878365f; // 1/sqrt(192)
    const int jmax = ((i >> 7) + 1) << 7;  // PV reads k < this bound
    int tid = threadIdx.x;
    int lane = tid & 31, warp = tid >> 5;
    __shared__ float redm[8], reds[8];

    float v[4];
    #pragma unroll
    for (int t = 0; t < 4; t++) {
        int j = tid + t * 256;
        v[t] = (j <= i) ? __half2float(row[j]) * scale : -FLT_MAX;
    }
    float mx = fmaxf(fmaxf(v[0], v[1]), fmaxf(v[2], v[3]));
    #pragma unroll
    for (int o = 16; o > 0; o >>= 1) mx = fmaxf(mx, __shfl_xor_sync(~0u, mx, o));
    if (lane == 0) redm[warp] = mx;
    __syncthreads();
    mx = redm[0];
    #pragma unroll
    for (int w = 1; w < 8; w++) mx = fmaxf(mx, redm[w]);

    float e[4];
    float sum = 0.f;
    #pragma unroll
    for (int t = 0; t < 4; t++) {
        int j = tid + t * 256;
        e[t] = (j <= i) ? __expf(v[t] - mx) : 0.f;
        sum += e[t];
    }
    #pragma unroll
    for (int o = 16; o > 0; o >>= 1) sum += __shfl_xor_sync(~0u, sum, o);
    if (lane == 0) reds[warp] = sum;
    __syncthreads();
    sum = 0.f;
    #pragma unroll
    for (int w = 0; w < 8; w++) sum += reds[w];
    float inv = 1.f / sum;

    #pragma unroll
    for (int t = 0; t < 4; t++) {
        int j = tid + t * 256;
        if (j < jmax) row[j] = __float2half_rn(e[t] * inv);
    }
}

// ---------------- host side -----------------------------------------------------
extern "C" void kernel_launch(void* const* d_in, const int* in_sizes, int n_in,
                              void* d_out, int out_size)
{
    const float* x     = (const float*)d_in[0];
    const float* Wqa   = (const float*)d_in[2];   // [7168,1536]
    const float* wqln  = (const float*)d_in[3];
    const float* Wqb   = (const float*)d_in[4];   // [1536,24576]
    const float* Wkva  = (const float*)d_in[5];   // [7168,576]
    const float* wkvln = (const float*)d_in[6];
    const float* Wkvb  = (const float*)d_in[7];   // [512,32768]
    const float* Wo    = (const float*)d_in[8];   // [16384,7168]
    float*       out   = (float*)d_out;

    float* qkva;
    cudaGetSymbolAddress((void**)&qkva, g_qkva);
    float* qkva1 = qkva + (long long)SQ * DPN;   // second split-K partial

    h16 *xh,*xl,*qkvah,*q16,*kv16,*kpe16,*Phb,*aoh;
    h16 *Wdt_h,*Wqb16,*Wkvb16,*Wo16;
    cudaGetSymbolAddress((void**)&xh,    g_xh);    cudaGetSymbolAddress((void**)&xl,    g_xl);
    cudaGetSymbolAddress((void**)&qkvah, g_qkvah);
    cudaGetSymbolAddress((void**)&q16,   g_q16);
    cudaGetSymbolAddress((void**)&kv16,  g_kv16);
    cudaGetSymbolAddress((void**)&kpe16, g_kpe16);
    cudaGetSymbolAddress((void**)&Phb,   g_Ph);
    cudaGetSymbolAddress((void**)&aoh,   g_aoh);
    cudaGetSymbolAddress((void**)&Wdt_h,  g_Wdt_h);
    cudaGetSymbolAddress((void**)&Wqb16,  g_Wqb16);
    cudaGetSymbolAddress((void**)&Wkvb16, g_Wkvb16);
    cudaGetSymbolAddress((void**)&Wo16,   g_Wo16);

    // 0) split x (hi+lo); weight prep
    split<true>(x, xh, xl, (long long)SQ * HID);
    tconv(Wqa,  HID, QLORA, QLORA, Wdt_h,                        HID);
    tconv(Wkva, HID, 576,   576,   Wdt_h + (long long)QLORA*HID, HID);
    split<false>(Wqb,  Wqb16,  Wqb16,  (long long)QLORA * NH * DQ);
    split<false>(Wkvb, Wkvb16, Wkvb16, (long long)KVLORA * NH * 256);
    split<false>(Wo,   Wo16,   Wo16,   (long long)NH * DV * HID);

    // 1) combined down-projection (2,1), split-K=2 via batch axis (272 CTAs)
    rung<2,1,false,false,false,false,false,false>(xh, xl, Wdt_h, Wdt_h, qkva,
        SQ, DPN, HID / 2, HID, HID, DPN,
        HID / 2, HID / 2, (long long)SQ * DPN, 2);

    // 2) k_pe rope (fp16 out) from partial sums; rmsnorms over partial sums
    rope_kpe2_kernel<<<(SQ * 32 + 255) / 256, 256>>>(
        qkva + QLORA + KVLORA, qkva1 + QLORA + KVLORA, DPN, kpe16);
    rmsnorm2_kernel<<<SQ, 256>>>(qkva,         qkva1,         wqln,  QLORA,  DPN);
    rmsnorm2_kernel<<<SQ, 256>>>(qkva + QLORA, qkva1 + QLORA, wkvln, KVLORA, DPN);

    // 3) convert activations; up-projections (1,1) BKN, fp16 out, M-fastest grid
    split<false>(qkva, qkvah, qkvah, (long long)SQ * DPN);
    rung<1,1,true,false,false,false,true,true>(qkvah, qkvah, Wqb16, Wqb16, (float*)q16,
        SQ, NH * DQ, QLORA, DPN, NH * DQ, NH * DQ, 0, 0, 0, 1);
    rung<1,1,true,false,false,false,true,true>(qkvah + QLORA, qkvah + QLORA, Wkvb16, Wkvb16, (float*)kv16,
        SQ, NH * 256, KVLORA, DPN, NH * 256, NH * 256, 0, 0, 0, 1);

    // 4) RoPE on fp16 q (in place); K and V both read in place downstream
    rope_q16_kernel<<<(SQ * NH * 32 + 255) / 256, 256>>>(q16);

    // 5) scores = Q @ K^T (1,1) BSC: k-chunks 0,1 from kv16 (k_nope), chunk 2 from kpe16
    rung<1,1,false,true,true,false,true,false>(q16, q16, kv16, kpe16, (float*)Phb,
        SQ, SQ, DQ, NH * DQ, NH * 256, SQ,
        DQ, 256, (long long)SQ * SQ, NH);

    // 6) causal softmax, fp16 in-place (scores -> P)
    softmax_p_kernel<<<NH * SQ, 256>>>(Phb);

    // 7) out_h = P @ V (1,1) BKN: V read directly from kv16, k-limited
    rung<1,1,true,false,false,true,true,false>(Phb, Phb, kv16 + DN, kv16 + DN, (float*)aoh,
        SQ, DV, SQ, SQ, NH * 256, NH * DV,
        (long long)SQ * SQ, 256, DV, NH);

    // 8) output projection (1,1) BKN, M-fastest grid
    rung<1,1,true,false,false,false,false,true>(aoh, aoh, Wo16, Wo16, out,
        SQ, HID, NH * DV, NH * DV, HID, HID, 0, 0, 0, 1);
}